// round 1
// baseline (speedup 1.0000x reference)
#include <cuda_runtime.h>
#include <cuda_bf16.h>
#include <math.h>

#define NN 23040          // nodes
#define NE 368640         // edges
#define NG 64             // graphs
#define TSEQ 360          // nodes per graph
#define HID 256
#define GOUT 16
#define LH 16

// ---------------- device scratch (static, no allocation) ----------------
__device__ int   g_deg[NN];            // incoming edge counts
__device__ float g_inv_sqrt[NN];
__device__ float g_inv_deg[NN];
__device__ int   g_row_ptr[NN + 1];
__device__ int   g_fill[NN];
__device__ int   g_col[NE];            // src per incoming edge (CSR by dst)
__device__ float g_bufA[NN * HID];     // gemm outputs
__device__ float g_bufB[NN * HID];     // layer outputs
__device__ float g_g16[NN * GOUT];
__device__ float g_h5[NN * GOUT];
__device__ float g_wx[2 * NN * 64];    // precomputed LSTM input gates
__device__ float g_hn[NG * 32];        // [hf | hb]

// ---------------- graph prep ----------------
__global__ void k_zero_deg() {
    int i = blockIdx.x * 256 + threadIdx.x;
    if (i < NN) g_deg[i] = 0;
}

__global__ void k_count(const int* __restrict__ dst) {
    int e = blockIdx.x * 256 + threadIdx.x;
    if (e < NE) atomicAdd(&g_deg[dst[e]], 1);
}

__global__ void k_nodeprep() {
    int i = blockIdx.x * 256 + threadIdx.x;
    if (i < NN) {
        float d = (float)g_deg[i] + 1.0f;
        g_inv_sqrt[i] = rsqrtf(d);
        g_inv_deg[i]  = 1.0f / d;
    }
}

// single-block exclusive scan of g_deg -> g_row_ptr, g_fill
__global__ void k_scan() {
    __shared__ int part[1024];
    const int CH = 23;                      // 1024*23 >= 23040
    int t = threadIdx.x;
    int s0 = t * CH;
    int s1 = s0 + CH; if (s1 > NN) s1 = NN;
    int s = 0;
    for (int i = s0; i < s1; i++) s += g_deg[i];
    part[t] = s;
    __syncthreads();
    for (int off = 1; off < 1024; off <<= 1) {
        int v = (t >= off) ? part[t - off] : 0;
        __syncthreads();
        part[t] += v;
        __syncthreads();
    }
    int run = part[t] - s;                  // exclusive prefix
    for (int i = s0; i < s1; i++) {
        g_row_ptr[i] = run;
        g_fill[i]    = run;
        run += g_deg[i];
    }
    if (t == 0) g_row_ptr[NN] = NE;
}

__global__ void k_scatter(const int* __restrict__ src, const int* __restrict__ dst) {
    int e = blockIdx.x * 256 + threadIdx.x;
    if (e < NE) {
        int d = dst[e];
        int p = atomicAdd(&g_fill[d], 1);
        g_col[p] = src[e];
    }
}

// ---------------- SGEMM 128x128x8, fp32, 256 threads, 8x8 per thread ----------------
__global__ __launch_bounds__(256) void k_sgemm(
    const float* __restrict__ A, const float* __restrict__ B, float* __restrict__ C,
    int M, int N, int K)
{
    __shared__ float As[8][128];
    __shared__ float Bs[8][128];
    int bm = blockIdx.y * 128, bn = blockIdx.x * 128;
    int tid = threadIdx.x;
    int ar = tid >> 1, ac = (tid & 1) * 4;
    int br = tid >> 5, bc = (tid & 31) * 4;
    int tr = (tid >> 4) * 8, tc = (tid & 15) * 8;
    float acc[8][8];
#pragma unroll
    for (int i = 0; i < 8; i++)
#pragma unroll
        for (int j = 0; j < 8; j++) acc[i][j] = 0.0f;

    for (int k0 = 0; k0 < K; k0 += 8) {
        float4 av = *(const float4*)&A[(size_t)(bm + ar) * K + k0 + ac];
        As[ac + 0][ar] = av.x; As[ac + 1][ar] = av.y;
        As[ac + 2][ar] = av.z; As[ac + 3][ar] = av.w;
        float4 bv = *(const float4*)&B[(size_t)(k0 + br) * N + bn + bc];
        *(float4*)&Bs[br][bc] = bv;
        __syncthreads();
#pragma unroll
        for (int kk = 0; kk < 8; kk++) {
            float4 a0 = *(float4*)&As[kk][tr];
            float4 a1 = *(float4*)&As[kk][tr + 4];
            float4 b0 = *(float4*)&Bs[kk][tc];
            float4 b1 = *(float4*)&Bs[kk][tc + 4];
            float a[8] = {a0.x, a0.y, a0.z, a0.w, a1.x, a1.y, a1.z, a1.w};
            float b[8] = {b0.x, b0.y, b0.z, b0.w, b1.x, b1.y, b1.z, b1.w};
#pragma unroll
            for (int i = 0; i < 8; i++)
#pragma unroll
                for (int j = 0; j < 8; j++) acc[i][j] = fmaf(a[i], b[j], acc[i][j]);
        }
        __syncthreads();
    }
#pragma unroll
    for (int i = 0; i < 8; i++) {
        float4 v0 = {acc[i][0], acc[i][1], acc[i][2], acc[i][3]};
        float4 v1 = {acc[i][4], acc[i][5], acc[i][6], acc[i][7]};
        size_t off = (size_t)(bm + tr + i) * N + bn + tc;
        *(float4*)&C[off]     = v0;
        *(float4*)&C[off + 4] = v1;
    }
}

// ---------------- GEMM to 16 outputs (layer 5) ----------------
__global__ __launch_bounds__(256) void k_gemm16(const float* __restrict__ A,
                                                const float* __restrict__ W)
{
    __shared__ float As[16][256];
    __shared__ float sW[256 * 16];
    int n0 = blockIdx.x * 16;
    int t = threadIdx.x;
#pragma unroll
    for (int i = 0; i < 16; i++) As[i][t] = A[(size_t)(n0 + i) * 256 + t];
#pragma unroll
    for (int i = 0; i < 16; i++) sW[i * 256 + t] = W[i * 256 + t];
    __syncthreads();
    int r = t >> 4, c = t & 15;
    float acc = 0.0f;
#pragma unroll 8
    for (int k = 0; k < 256; k++) acc = fmaf(As[r][k], sW[k * 16 + c], acc);
    g_g16[(size_t)(n0 + r) * 16 + c] = acc;
}

// ---------------- GCN aggregation: out = relu(sum_in norm*g[src] + g*inv_deg + b) ----------------
template <int W>
__global__ void k_agg(const float* __restrict__ gbuf, const float* __restrict__ bias,
                      float* __restrict__ obuf)
{
    int node = blockIdx.x * (256 / W) + threadIdx.x / W;
    int c = threadIdx.x % W;
    float isd = g_inv_sqrt[node];
    float acc = gbuf[(size_t)node * W + c] * g_inv_deg[node];
    int e0 = g_row_ptr[node], e1 = g_row_ptr[node + 1];
    for (int e = e0; e < e1; e++) {
        int s = g_col[e];
        acc = fmaf(gbuf[(size_t)s * W + c], g_inv_sqrt[s] * isd, acc);
    }
    acc += bias[c];
    obuf[(size_t)node * W + c] = acc > 0.0f ? acc : 0.0f;
}

// ---------------- LSTM ----------------
__global__ void k_lstm_pre(const float* __restrict__ Wih_f, const float* __restrict__ bih_f,
                           const float* __restrict__ bhh_f,
                           const float* __restrict__ Wih_b, const float* __restrict__ bih_b,
                           const float* __restrict__ bhh_b)
{
    __shared__ float xr[16];
    int node = blockIdx.x;
    int t = threadIdx.x;
    if (t < 16) xr[t] = g_h5[node * 16 + t];
    __syncthreads();
    int d = t >> 6, r = t & 63;
    const float* Wp = d ? Wih_b : Wih_f;
    float acc = d ? (bih_b[r] + bhh_b[r]) : (bih_f[r] + bhh_f[r]);
#pragma unroll
    for (int k = 0; k < 16; k++) acc = fmaf(xr[k], Wp[r * 16 + k], acc);
    g_wx[((size_t)d * NN + node) * 64 + r] = acc;
}

__device__ __forceinline__ float sigm_(float x) { return 1.0f / (1.0f + __expf(-x)); }
__device__ __forceinline__ float tanh_(float x) { return 2.0f / (1.0f + __expf(-2.0f * x)) - 1.0f; }

__global__ void k_lstm_rec(const float* __restrict__ Whh_f, const float* __restrict__ Whh_b)
{
    int wid = blockIdx.x * (blockDim.x / 32) + threadIdx.x / 32;  // 0..127
    int lane = threadIdx.x & 31;
    int d = wid & 1, g = wid >> 1;
    const float* Whh = d ? Whh_b : Whh_f;
    float w0[16], w1[16];
#pragma unroll
    for (int j = 0; j < 16; j++) {
        w0[j] = Whh[lane * 16 + j];
        w1[j] = Whh[(lane + 32) * 16 + j];
    }
    float h = 0.0f, c = 0.0f;
    const float* wx = g_wx + ((size_t)d * NN + (size_t)g * TSEQ) * 64;
    for (int t = 0; t < TSEQ; t++) {
        int tt = d ? (TSEQ - 1 - t) : t;
        const float* wxt = wx + (size_t)tt * 64;
        float g0 = wxt[lane], g1 = wxt[32 + lane];
#pragma unroll
        for (int j = 0; j < 16; j++) {
            float hv = __shfl_sync(0xffffffffu, h, j);
            g0 = fmaf(hv, w0[j], g0);
            g1 = fmaf(hv, w1[j], g1);
        }
        // lane k<16: i=g0, g(gate)=g1; f on lane k+16 (g0), o on lane k+16 (g1)
        float fk = __shfl_sync(0xffffffffu, g0, (lane & 15) + 16);
        float ok = __shfl_sync(0xffffffffu, g1, (lane & 15) + 16);
        float cn = sigm_(fk) * c + sigm_(g0) * tanh_(g1);
        float hv2 = sigm_(ok) * tanh_(cn);
        c = cn;
        h = hv2;
    }
    if (lane < 16) g_hn[g * 32 + d * 16 + lane] = h;
}

// ---------------- final MLP ----------------
__global__ void k_mlp(const float* __restrict__ Wm1, const float* __restrict__ bm1,
                      const float* __restrict__ Wm2, const float* __restrict__ bm2,
                      float* __restrict__ out)
{
    __shared__ float hs[32];
    __shared__ float red[128];
    int g = blockIdx.x;
    int t = threadIdx.x;
    if (t < 32) hs[t] = g_hn[g * 32 + t];
    __syncthreads();
    float a = bm1[t];
#pragma unroll
    for (int k = 0; k < 32; k++) a = fmaf(hs[k], Wm1[k * 128 + t], a);
    a = (a > 0.0f ? a : 0.0f) * Wm2[t];
    red[t] = a;
    __syncthreads();
    for (int s = 64; s > 0; s >>= 1) {
        if (t < s) red[t] += red[t + s];
        __syncthreads();
    }
    if (t == 0) out[g] = red[0] + bm2[0];
}

// ---------------- launch ----------------
static float* symf(const void* sym) {
    void* p = nullptr;
    cudaGetSymbolAddress(&p, sym);
    return (float*)p;
}

extern "C" void kernel_launch(void* const* d_in, const int* in_sizes, int n_in,
                              void* d_out, int out_size)
{
    const float* x   = (const float*)d_in[0];
    const int*   ei  = (const int*)d_in[1];
    const int*   src = ei;
    const int*   dst = ei + NE;
    const float* W1 = (const float*)d_in[3],  *b1 = (const float*)d_in[4];
    const float* W2 = (const float*)d_in[5],  *b2 = (const float*)d_in[6];
    const float* W3 = (const float*)d_in[7],  *b3 = (const float*)d_in[8];
    const float* W4 = (const float*)d_in[9],  *b4 = (const float*)d_in[10];
    const float* W5 = (const float*)d_in[11], *b5 = (const float*)d_in[12];
    const float* Wih_f = (const float*)d_in[13], *Whh_f = (const float*)d_in[14];
    const float* bih_f = (const float*)d_in[15], *bhh_f = (const float*)d_in[16];
    const float* Wih_b = (const float*)d_in[17], *Whh_b = (const float*)d_in[18];
    const float* bih_b = (const float*)d_in[19], *bhh_b = (const float*)d_in[20];
    const float* Wm1 = (const float*)d_in[21], *bm1 = (const float*)d_in[22];
    const float* Wm2 = (const float*)d_in[23], *bm2 = (const float*)d_in[24];
    float* out = (float*)d_out;

    float* bufA = symf(g_bufA);
    float* bufB = symf(g_bufB);

    // graph prep
    k_zero_deg<<<(NN + 255) / 256, 256>>>();
    k_count<<<NE / 256, 256>>>(dst);
    k_nodeprep<<<(NN + 255) / 256, 256>>>();
    k_scan<<<1, 1024>>>();
    k_scatter<<<NE / 256, 256>>>(src, dst);

    dim3 grid1(HID / 128, NN / 128);   // (2, 180)
    // layer 1
    k_sgemm<<<grid1, 256>>>(x, W1, bufA, NN, HID, 3000);
    k_agg<HID><<<NN, 256>>>(bufA, b1, bufB);
    // layers 2-4
    k_sgemm<<<grid1, 256>>>(bufB, W2, bufA, NN, HID, HID);
    k_agg<HID><<<NN, 256>>>(bufA, b2, bufB);
    k_sgemm<<<grid1, 256>>>(bufB, W3, bufA, NN, HID, HID);
    k_agg<HID><<<NN, 256>>>(bufA, b3, bufB);
    k_sgemm<<<grid1, 256>>>(bufB, W4, bufA, NN, HID, HID);
    k_agg<HID><<<NN, 256>>>(bufA, b4, bufB);
    // layer 5 (width 16)
    k_gemm16<<<NN / 16, 256>>>(bufB, W5);
    k_agg<GOUT><<<NN / (256 / GOUT), 256>>>(symf(g_g16), b5, symf(g_h5));

    // LSTM
    k_lstm_pre<<<NN, 128>>>(Wih_f, bih_f, bhh_f, Wih_b, bih_b, bhh_b);
    k_lstm_rec<<<32, 128>>>(Whh_f, Whh_b);

    // MLP head
    k_mlp<<<NG, 128>>>(Wm1, bm1, Wm2, bm2, out);
}

// round 3
// speedup vs baseline: 1.7244x; 1.7244x over previous
#include <cuda_runtime.h>
#include <cuda_bf16.h>
#include <math.h>
#include <stdint.h>

#define NN 23040          // nodes
#define NE 368640         // edges
#define NG 64             // graphs
#define TSEQ 360          // nodes per graph
#define HID 256
#define GOUT 16
#define LH 16
#define KP1 3008          // layer-1 K padded to 32

// ======================= device scratch (static) =======================
__device__ int   g_deg[NN];
__device__ float g_inv_sqrt[NN];
__device__ float g_inv_deg[NN];
__device__ int   g_row_ptr[NN + 1];
__device__ int   g_fill[NN];
__device__ int   g_col[NE];
__device__ int   g_excl[NN];
__device__ int   g_bsum[90];
__device__ int   g_boff[128];
__device__ float g_bufA[NN * HID];
__device__ float g_bufB[NN * HID];
__device__ float g_g16[NN * GOUT];
__device__ float g_h5[NN * GOUT];
__device__ float g_wx[2 * NN * 64];
__device__ float g_hn[NG * 32];
// weight hi/lo bf16, layout [256][KP] k-contiguous
__device__ __align__(16) __nv_bfloat16 g_Wh[256 * KP1];
__device__ __align__(16) __nv_bfloat16 g_Wl[256 * KP1];

// ======================= graph prep =======================
__global__ void k_zero_deg() {
    int i = blockIdx.x * 256 + threadIdx.x;
    if (i < NN) g_deg[i] = 0;
}
__global__ void k_count(const int* __restrict__ dst) {
    int e = blockIdx.x * 256 + threadIdx.x;
    if (e < NE) atomicAdd(&g_deg[dst[e]], 1);
}
__global__ void k_nodeprep() {
    int i = blockIdx.x * 256 + threadIdx.x;
    if (i < NN) {
        float d = (float)g_deg[i] + 1.0f;
        g_inv_sqrt[i] = rsqrtf(d);
        g_inv_deg[i]  = 1.0f / d;
    }
}
__global__ void k_scan1() {
    __shared__ int sh[256];
    int t = threadIdx.x;
    int i = blockIdx.x * 256 + t;
    int v = g_deg[i];
    sh[t] = v;
    __syncthreads();
    for (int off = 1; off < 256; off <<= 1) {
        int add = (t >= off) ? sh[t - off] : 0;
        __syncthreads();
        sh[t] += add;
        __syncthreads();
    }
    g_excl[i] = sh[t] - v;
    if (t == 255) g_bsum[blockIdx.x] = sh[t];
}
__global__ void k_scan2() {
    __shared__ int sh[128];
    int t = threadIdx.x;
    int v = (t < 90) ? g_bsum[t] : 0;
    sh[t] = v;
    __syncthreads();
    for (int off = 1; off < 128; off <<= 1) {
        int add = (t >= off) ? sh[t - off] : 0;
        __syncthreads();
        sh[t] += add;
        __syncthreads();
    }
    if (t < 90) g_boff[t] = sh[t] - v;
}
__global__ void k_scan3() {
    int i = blockIdx.x * 256 + threadIdx.x;
    int rp = g_excl[i] + g_boff[blockIdx.x];
    g_row_ptr[i] = rp;
    g_fill[i] = rp;
    if (i == 0) g_row_ptr[NN] = NE;
}
__global__ void k_scatter(const int* __restrict__ src, const int* __restrict__ dst) {
    int e = blockIdx.x * 256 + threadIdx.x;
    if (e < NE) {
        int d = dst[e];
        int p = atomicAdd(&g_fill[d], 1);
        g_col[p] = src[e];
    }
}

// ======================= weight convert: W[K][256] fp32 -> Wh/Wl [256][KP] bf16 =======================
__global__ void k_convW(const float* __restrict__ W, int K, int KPad) {
    int idx = blockIdx.x * 256 + threadIdx.x;
    if (idx >= 256 * KPad) return;
    int n = idx / KPad;
    int k = idx % KPad;
    float v = (k < K) ? W[(size_t)k * 256 + n] : 0.0f;
    __nv_bfloat16 h = __float2bfloat16_rn(v);
    __nv_bfloat16 l = __float2bfloat16_rn(v - __bfloat162float(h));
    g_Wh[idx] = h;
    g_Wl[idx] = l;
}

// ======================= HMMA GEMM: C[M,256] = A[M,K] @ W[K,256] =======================
// bf16 hi/lo split: AhBh + AlBh + AhBl, fp32 accumulate.
// CTA 128x256, 256 threads = 8 warps, warp tile 64x64.
// smem per stage: Ah[128][40] Al[128][40] Bh[256][40] Bl[256][40] halves (stride 40 halves = 80B)
#define AROWS 40               // padded row stride in halves
#define ST_AH 0
#define ST_AL 10240
#define ST_BH 20480
#define ST_BL 40960
#define STAGE_BYTES 61440
#define SMEM_TOTAL (2 * STAGE_BYTES)

__device__ __forceinline__ uint32_t smem_u32(const void* p) {
    uint32_t a;
    asm("{ .reg .u64 t; cvta.to.shared.u64 t, %1; cvt.u32.u64 %0, t; }" : "=r"(a) : "l"(p));
    return a;
}
__device__ __forceinline__ void cp16(uint32_t dst, const void* src) {
    asm volatile("cp.async.cg.shared.global [%0], [%1], 16;" :: "r"(dst), "l"(src) : "memory");
}
__device__ __forceinline__ void mma_bf16(float* d, const uint32_t* a, const uint32_t* b) {
    asm volatile(
        "mma.sync.aligned.m16n8k16.row.col.f32.bf16.bf16.f32 "
        "{%0,%1,%2,%3}, {%4,%5,%6,%7}, {%8,%9}, {%0,%1,%2,%3};"
        : "+f"(d[0]), "+f"(d[1]), "+f"(d[2]), "+f"(d[3])
        : "r"(a[0]), "r"(a[1]), "r"(a[2]), "r"(a[3]), "r"(b[0]), "r"(b[1]));
}

__global__ __launch_bounds__(256, 1) void k_mma(
    const float* __restrict__ A, const __nv_bfloat16* __restrict__ Wh,
    const __nv_bfloat16* __restrict__ Wl, float* __restrict__ C,
    int K, int KPad)
{
    extern __shared__ __align__(16) char smem[];
    const int tid = threadIdx.x;
    const int wid = tid >> 5, lane = tid & 31;
    const int g = lane >> 2, t4 = lane & 3;
    const int wm = wid >> 2, wn = wid & 3;     // warp grid 2(M) x 4(N)
    const int bm = blockIdx.x * 128;
    const int NC = KPad / 32;

    float acc[4][8][4];
#pragma unroll
    for (int mi = 0; mi < 4; mi++)
#pragma unroll
        for (int ni = 0; ni < 8; ni++)
#pragma unroll
            for (int q = 0; q < 4; q++) acc[mi][ni][q] = 0.0f;

    // A-tile register staging (128x32 fp32 / 256 thr = 4 float4 per thread)
    float4 areg[4];
    const int arow[1] = {0};
    (void)arow;

    // ---- helpers inlined manually ----
    // A slots: s = i*256+tid : row = s>>3 (0..127), seg = s&7 (float4 within 32 floats)
    // B slots: s = i*256+tid : row = s>>2 (0..255), seg = s&3 (16B within 64B row)

    auto ldA = [&](int c) {
        const int k0 = c * 32;
#pragma unroll
        for (int i = 0; i < 4; i++) {
            int s = i * 256 + tid;
            int r = s >> 3, seg = s & 7;
            int kk = k0 + seg * 4;
            if (kk + 3 < K) {
                areg[i] = *(const float4*)&A[(size_t)(bm + r) * K + kk];
            } else {
                float tmp[4];
#pragma unroll
                for (int j = 0; j < 4; j++)
                    tmp[j] = (kk + j < K) ? A[(size_t)(bm + r) * K + kk + j] : 0.0f;
                areg[i] = make_float4(tmp[0], tmp[1], tmp[2], tmp[3]);
            }
        }
    };
    auto stA = [&](int p) {
        char* base = smem + p * STAGE_BYTES;
#pragma unroll
        for (int i = 0; i < 4; i++) {
            int s = i * 256 + tid;
            int r = s >> 3, seg = s & 7;
            float4 v = areg[i];
            __nv_bfloat16 h0 = __float2bfloat16_rn(v.x), h1 = __float2bfloat16_rn(v.y);
            __nv_bfloat16 h2 = __float2bfloat16_rn(v.z), h3 = __float2bfloat16_rn(v.w);
            __nv_bfloat16 l0 = __float2bfloat16_rn(v.x - __bfloat162float(h0));
            __nv_bfloat16 l1 = __float2bfloat16_rn(v.y - __bfloat162float(h1));
            __nv_bfloat16 l2 = __float2bfloat16_rn(v.z - __bfloat162float(h2));
            __nv_bfloat16 l3 = __float2bfloat16_rn(v.w - __bfloat162float(h3));
            uint2 uh, ul;
            uh.x = ((uint32_t)__bfloat16_as_ushort(h1) << 16) | __bfloat16_as_ushort(h0);
            uh.y = ((uint32_t)__bfloat16_as_ushort(h3) << 16) | __bfloat16_as_ushort(h2);
            ul.x = ((uint32_t)__bfloat16_as_ushort(l1) << 16) | __bfloat16_as_ushort(l0);
            ul.y = ((uint32_t)__bfloat16_as_ushort(l3) << 16) | __bfloat16_as_ushort(l2);
            int off = r * 80 + seg * 8;
            *(uint2*)(base + ST_AH + off) = uh;
            *(uint2*)(base + ST_AL + off) = ul;
        }
    };
    auto cpB = [&](int c, int p) {
        const int k0 = c * 32;
        char* base = smem + p * STAGE_BYTES;
        uint32_t bh = smem_u32(base + ST_BH);
        uint32_t bl = smem_u32(base + ST_BL);
#pragma unroll
        for (int i = 0; i < 4; i++) {
            int s = i * 256 + tid;
            int r = s >> 2, seg = s & 3;
            int off = r * 80 + seg * 16;
            size_t goff = (size_t)r * KPad + k0 + seg * 8;
            cp16(bh + off, Wh + goff);
            cp16(bl + off, Wl + goff);
        }
        asm volatile("cp.async.commit_group;" ::: "memory");
    };

    // prologue: chunk 0
    ldA(0);
    cpB(0, 0);
    stA(0);
    asm volatile("cp.async.wait_group 0;" ::: "memory");
    __syncthreads();

    for (int c = 0; c < NC; c++) {
        const int p = c & 1;
        if (c + 1 < NC) {
            ldA(c + 1);
            cpB(c + 1, p ^ 1);
        }

        // ---- compute chunk c from stage p ----
        const uint16_t* AhS = (const uint16_t*)(smem + p * STAGE_BYTES + ST_AH);
        const uint16_t* AlS = (const uint16_t*)(smem + p * STAGE_BYTES + ST_AL);
        const uint16_t* BhS = (const uint16_t*)(smem + p * STAGE_BYTES + ST_BH);
        const uint16_t* BlS = (const uint16_t*)(smem + p * STAGE_BYTES + ST_BL);
#pragma unroll
        for (int ks = 0; ks < 2; ks++) {
            const int kofs = ks * 16;
            // B fragments for this warp's 8 n-tiles
            uint32_t bh[8][2], bl[8][2];
#pragma unroll
            for (int ni = 0; ni < 8; ni++) {
                int n0 = wn * 64 + ni * 8 + g;
                int c0 = kofs + 2 * t4;
                bh[ni][0] = *(const uint32_t*)&BhS[n0 * AROWS + c0];
                bh[ni][1] = *(const uint32_t*)&BhS[n0 * AROWS + c0 + 8];
                bl[ni][0] = *(const uint32_t*)&BlS[n0 * AROWS + c0];
                bl[ni][1] = *(const uint32_t*)&BlS[n0 * AROWS + c0 + 8];
            }
#pragma unroll
            for (int mi = 0; mi < 4; mi++) {
                int r0 = wm * 64 + mi * 16 + g;
                int c0 = kofs + 2 * t4;
                uint32_t ah[4], al[4];
                ah[0] = *(const uint32_t*)&AhS[r0 * AROWS + c0];
                ah[1] = *(const uint32_t*)&AhS[(r0 + 8) * AROWS + c0];
                ah[2] = *(const uint32_t*)&AhS[r0 * AROWS + c0 + 8];
                ah[3] = *(const uint32_t*)&AhS[(r0 + 8) * AROWS + c0 + 8];
                al[0] = *(const uint32_t*)&AlS[r0 * AROWS + c0];
                al[1] = *(const uint32_t*)&AlS[(r0 + 8) * AROWS + c0];
                al[2] = *(const uint32_t*)&AlS[r0 * AROWS + c0 + 8];
                al[3] = *(const uint32_t*)&AlS[(r0 + 8) * AROWS + c0 + 8];
#pragma unroll
                for (int ni = 0; ni < 8; ni++) {
                    mma_bf16(acc[mi][ni], ah, bh[ni]);
                    mma_bf16(acc[mi][ni], al, bh[ni]);
                    mma_bf16(acc[mi][ni], ah, bl[ni]);
                }
            }
        }

        if (c + 1 < NC) stA(p ^ 1);
        asm volatile("cp.async.wait_group 0;" ::: "memory");
        __syncthreads();
    }

    // ---- epilogue ----
#pragma unroll
    for (int mi = 0; mi < 4; mi++) {
        int row = bm + wm * 64 + mi * 16 + g;
#pragma unroll
        for (int ni = 0; ni < 8; ni++) {
            int col = wn * 64 + ni * 8 + 2 * t4;
            float2 v0 = make_float2(acc[mi][ni][0], acc[mi][ni][1]);
            float2 v1 = make_float2(acc[mi][ni][2], acc[mi][ni][3]);
            *(float2*)&C[(size_t)row * 256 + col] = v0;
            *(float2*)&C[(size_t)(row + 8) * 256 + col] = v1;
        }
    }
}

// ======================= layer-5 GEMM (256 -> 16) =======================
__global__ __launch_bounds__(256) void k_gemm16(const float* __restrict__ A,
                                                const float* __restrict__ W)
{
    __shared__ float As[16][256];
    __shared__ float sW[256 * 16];
    int n0 = blockIdx.x * 16;
    int t = threadIdx.x;
#pragma unroll
    for (int i = 0; i < 16; i++) As[i][t] = A[(size_t)(n0 + i) * 256 + t];
#pragma unroll
    for (int i = 0; i < 16; i++) sW[i * 256 + t] = W[i * 256 + t];
    __syncthreads();
    int r = t >> 4, c = t & 15;
    float acc = 0.0f;
#pragma unroll 8
    for (int k = 0; k < 256; k++) acc = fmaf(As[r][k], sW[k * 16 + c], acc);
    g_g16[(size_t)(n0 + r) * 16 + c] = acc;
}

// ======================= GCN aggregation =======================
template <int W>
__global__ void k_agg(const float* __restrict__ gbuf, const float* __restrict__ bias,
                      float* __restrict__ obuf)
{
    int node = blockIdx.x * (256 / W) + threadIdx.x / W;
    int c = threadIdx.x % W;
    float isd = g_inv_sqrt[node];
    float acc = gbuf[(size_t)node * W + c] * g_inv_deg[node];
    int e0 = g_row_ptr[node], e1 = g_row_ptr[node + 1];
    for (int e = e0; e < e1; e++) {
        int s = g_col[e];
        acc = fmaf(gbuf[(size_t)s * W + c], g_inv_sqrt[s] * isd, acc);
    }
    acc += bias[c];
    obuf[(size_t)node * W + c] = acc > 0.0f ? acc : 0.0f;
}

// ======================= LSTM =======================
__global__ void k_lstm_pre(const float* __restrict__ Wih_f, const float* __restrict__ bih_f,
                           const float* __restrict__ bhh_f,
                           const float* __restrict__ Wih_b, const float* __restrict__ bih_b,
                           const float* __restrict__ bhh_b)
{
    __shared__ float xr[16];
    int node = blockIdx.x;
    int t = threadIdx.x;
    if (t < 16) xr[t] = g_h5[node * 16 + t];
    __syncthreads();
    int d = t >> 6, r = t & 63;
    const float* Wp = d ? Wih_b : Wih_f;
    float acc = d ? (bih_b[r] + bhh_b[r]) : (bih_f[r] + bhh_f[r]);
#pragma unroll
    for (int k = 0; k < 16; k++) acc = fmaf(xr[k], Wp[r * 16 + k], acc);
    g_wx[((size_t)d * NN + node) * 64 + r] = acc;
}

__device__ __forceinline__ float sigm_(float x) { return 1.0f / (1.0f + __expf(-x)); }

__global__ void k_lstm_rec(const float* __restrict__ Whh_f, const float* __restrict__ Whh_b)
{
    int wid = blockIdx.x * (blockDim.x / 32) + threadIdx.x / 32;
    int lane = threadIdx.x & 31;
    int d = wid & 1, g = wid >> 1;
    const float* Whh = d ? Whh_b : Whh_f;
    float w0[16], w1[16];
#pragma unroll
    for (int j = 0; j < 16; j++) {
        w0[j] = Whh[lane * 16 + j];
        w1[j] = Whh[(lane + 32) * 16 + j];
    }
    float h = 0.0f, c = 0.0f;
    const float* wx = g_wx + ((size_t)d * NN + (size_t)g * TSEQ) * 64;
    for (int t = 0; t < TSEQ; t++) {
        int tt = d ? (TSEQ - 1 - t) : t;
        const float* wxt = wx + (size_t)tt * 64;
        float g0 = wxt[lane], g1 = wxt[32 + lane];
#pragma unroll
        for (int j = 0; j < 16; j++) {
            float hv = __shfl_sync(0xffffffffu, h, j);
            g0 = fmaf(hv, w0[j], g0);
            g1 = fmaf(hv, w1[j], g1);
        }
        float fk = __shfl_sync(0xffffffffu, g0, (lane & 15) + 16);
        float ok = __shfl_sync(0xffffffffu, g1, (lane & 15) + 16);
        float cn = sigm_(fk) * c + sigm_(g0) * tanhf(g1);
        float hv2 = sigm_(ok) * tanhf(cn);
        c = cn;
        h = hv2;
    }
    if (lane < 16) g_hn[g * 32 + d * 16 + lane] = h;
}

// ======================= final MLP =======================
__global__ void k_mlp(const float* __restrict__ Wm1, const float* __restrict__ bm1,
                      const float* __restrict__ Wm2, const float* __restrict__ bm2,
                      float* __restrict__ out)
{
    __shared__ float hs[32];
    __shared__ float red[128];
    int g = blockIdx.x;
    int t = threadIdx.x;
    if (t < 32) hs[t] = g_hn[g * 32 + t];
    __syncthreads();
    float a = bm1[t];
#pragma unroll
    for (int k = 0; k < 32; k++) a = fmaf(hs[k], Wm1[k * 128 + t], a);
    a = (a > 0.0f ? a : 0.0f) * Wm2[t];
    red[t] = a;
    __syncthreads();
    for (int s = 64; s > 0; s >>= 1) {
        if (t < s) red[t] += red[t + s];
        __syncthreads();
    }
    if (t == 0) out[g] = red[0] + bm2[0];
}

// ======================= launch =======================
static void* symp(const void* sym) {
    void* p = nullptr;
    cudaGetSymbolAddress(&p, sym);
    return p;
}

extern "C" void kernel_launch(void* const* d_in, const int* in_sizes, int n_in,
                              void* d_out, int out_size)
{
    const float* x   = (const float*)d_in[0];
    const int*   ei  = (const int*)d_in[1];
    const int*   src = ei;
    const int*   dst = ei + NE;
    const float* W1 = (const float*)d_in[3],  *b1 = (const float*)d_in[4];
    const float* W2 = (const float*)d_in[5],  *b2 = (const float*)d_in[6];
    const float* W3 = (const float*)d_in[7],  *b3 = (const float*)d_in[8];
    const float* W4 = (const float*)d_in[9],  *b4 = (const float*)d_in[10];
    const float* W5 = (const float*)d_in[11], *b5 = (const float*)d_in[12];
    const float* Wih_f = (const float*)d_in[13], *Whh_f = (const float*)d_in[14];
    const float* bih_f = (const float*)d_in[15], *bhh_f = (const float*)d_in[16];
    const float* Wih_b = (const float*)d_in[17], *Whh_b = (const float*)d_in[18];
    const float* bih_b = (const float*)d_in[19], *bhh_b = (const float*)d_in[20];
    const float* Wm1 = (const float*)d_in[21], *bm1 = (const float*)d_in[22];
    const float* Wm2 = (const float*)d_in[23], *bm2 = (const float*)d_in[24];
    float* out = (float*)d_out;

    float* bufA = (float*)symp(g_bufA);
    float* bufB = (float*)symp(g_bufB);
    const __nv_bfloat16* Wh = (const __nv_bfloat16*)symp(g_Wh);
    const __nv_bfloat16* Wl = (const __nv_bfloat16*)symp(g_Wl);

    cudaFuncSetAttribute(k_mma, cudaFuncAttributeMaxDynamicSharedMemorySize, SMEM_TOTAL);

    // graph prep
    k_zero_deg<<<(NN + 255) / 256, 256>>>();
    k_count<<<NE / 256, 256>>>(dst);
    k_nodeprep<<<(NN + 255) / 256, 256>>>();
    k_scan1<<<90, 256>>>();
    k_scan2<<<1, 128>>>();
    k_scan3<<<90, 256>>>();
    k_scatter<<<NE / 256, 256>>>(src, dst);

    // layer 1 (K=3000, padded 3008)
    k_convW<<<(256 * KP1 + 255) / 256, 256>>>(W1, 3000, KP1);
    k_mma<<<NN / 128, 256, SMEM_TOTAL>>>(x, Wh, Wl, bufA, 3000, KP1);
    k_agg<HID><<<NN, 256>>>(bufA, b1, bufB);
    // layers 2-4 (K=256)
    const float* Ws[3] = {W2, W3, W4};
    const float* bs[3] = {b2, b3, b4};
    for (int l = 0; l < 3; l++) {
        k_convW<<<(256 * 256 + 255) / 256, 256>>>(Ws[l], 256, 256);
        k_mma<<<NN / 128, 256, SMEM_TOTAL>>>(bufB, Wh, Wl, bufA, 256, 256);
        k_agg<HID><<<NN, 256>>>(bufA, bs[l], bufB);
    }
    // layer 5
    k_gemm16<<<NN / 16, 256>>>(bufB, W5);
    k_agg<GOUT><<<NN / (256 / GOUT), 256>>>((const float*)symp(g_g16), b5, (float*)symp(g_h5));

    // LSTM
    k_lstm_pre<<<NN, 128>>>(Wih_f, bih_f, bhh_f, Wih_b, bih_b, bhh_b);
    k_lstm_rec<<<32, 128>>>(Whh_f, Whh_b);

    // MLP head
    k_mlp<<<NG, 128>>>(Wm1, bm1, Wm2, bm2, out);
}

// round 4
// speedup vs baseline: 2.0100x; 1.1656x over previous
#include <cuda_runtime.h>
#include <cuda_bf16.h>
#include <math.h>
#include <stdint.h>

#define NN 23040          // nodes
#define NE 368640         // edges
#define NG 64             // graphs
#define TSEQ 360          // nodes per graph
#define HID 256
#define GOUT 16
#define LH 16
#define KP1 3008          // layer-1 K padded to 32

// ======================= device scratch (static) =======================
__device__ int   g_deg[NN];
__device__ float g_inv_sqrt[NN];
__device__ float g_inv_deg[NN];
__device__ int   g_row_ptr[NN + 1];
__device__ int   g_fill[NN];
__device__ int   g_col[NE];
__device__ int   g_excl[NN];
__device__ int   g_bsum[90];
__device__ int   g_boff[128];
__device__ __align__(16) float g_bufA[NN * HID];
__device__ __align__(16) float g_bufB[NN * HID];
__device__ __align__(16) float g_g16[NN * GOUT];
__device__ __align__(16) float g_h5[NN * GOUT];
__device__ float g_wx[2 * NN * 64];
__device__ float g_hn[NG * 32];
// weight hi/lo bf16, layout [256][KP] k-contiguous
__device__ __align__(16) __nv_bfloat16 g_Wh[256 * KP1];
__device__ __align__(16) __nv_bfloat16 g_Wl[256 * KP1];

// ======================= graph prep =======================
__global__ void k_zero_deg() {
    int i = blockIdx.x * 256 + threadIdx.x;
    if (i < NN) g_deg[i] = 0;
}
__global__ void k_count(const int* __restrict__ dst) {
    int e = blockIdx.x * 256 + threadIdx.x;
    if (e < NE) atomicAdd(&g_deg[dst[e]], 1);
}
__global__ void k_nodeprep() {
    int i = blockIdx.x * 256 + threadIdx.x;
    if (i < NN) {
        float d = (float)g_deg[i] + 1.0f;
        g_inv_sqrt[i] = rsqrtf(d);
        g_inv_deg[i]  = 1.0f / d;
    }
}
__global__ void k_scan1() {
    __shared__ int sh[256];
    int t = threadIdx.x;
    int i = blockIdx.x * 256 + t;
    int v = g_deg[i];
    sh[t] = v;
    __syncthreads();
    for (int off = 1; off < 256; off <<= 1) {
        int add = (t >= off) ? sh[t - off] : 0;
        __syncthreads();
        sh[t] += add;
        __syncthreads();
    }
    g_excl[i] = sh[t] - v;
    if (t == 255) g_bsum[blockIdx.x] = sh[t];
}
__global__ void k_scan2() {
    __shared__ int sh[128];
    int t = threadIdx.x;
    int v = (t < 90) ? g_bsum[t] : 0;
    sh[t] = v;
    __syncthreads();
    for (int off = 1; off < 128; off <<= 1) {
        int add = (t >= off) ? sh[t - off] : 0;
        __syncthreads();
        sh[t] += add;
        __syncthreads();
    }
    if (t < 90) g_boff[t] = sh[t] - v;
}
__global__ void k_scan3() {
    int i = blockIdx.x * 256 + threadIdx.x;
    int rp = g_excl[i] + g_boff[blockIdx.x];
    g_row_ptr[i] = rp;
    g_fill[i] = rp;
    if (i == 0) g_row_ptr[NN] = NE;
}
__global__ void k_scatter(const int* __restrict__ src, const int* __restrict__ dst) {
    int e = blockIdx.x * 256 + threadIdx.x;
    if (e < NE) {
        int d = dst[e];
        int p = atomicAdd(&g_fill[d], 1);
        g_col[p] = src[e];
    }
}

// ======================= weight convert (coalesced transpose) =======================
// W fp32 [K][256] -> g_Wh/g_Wl bf16 [256][KPad]
__global__ void k_convW(const float* __restrict__ W, int K, int KPad) {
    __shared__ float tile[32][33];
    int kb = blockIdx.x * 32, nb = blockIdx.y * 32;
    int tx = threadIdx.x, ty = threadIdx.y;   // 32 x 8
#pragma unroll
    for (int i = ty; i < 32; i += 8) {
        int k = kb + i;
        tile[i][tx] = (k < K) ? W[(size_t)k * 256 + nb + tx] : 0.0f;
    }
    __syncthreads();
#pragma unroll
    for (int i = ty; i < 32; i += 8) {
        int n = nb + i, k = kb + tx;
        float v = tile[tx][i];
        __nv_bfloat16 h = __float2bfloat16_rn(v);
        __nv_bfloat16 l = __float2bfloat16_rn(v - __bfloat162float(h));
        size_t o = (size_t)n * KPad + k;
        g_Wh[o] = h;
        g_Wl[o] = l;
    }
}

// ======================= HMMA GEMM: C[M,256] = A[M,K] @ W[K,256] =======================
// bf16 hi/lo split: AhBh + AlBh + AhBl, fp32 accumulate.
// CTA 128x256, 256 threads = 8 warps, warp tile 64x64.
#define AROWS 40               // padded row stride in halves
#define ST_AH 0
#define ST_AL 10240
#define ST_BH 20480
#define ST_BL 40960
#define STAGE_BYTES 61440
#define SMEM_TOTAL (2 * STAGE_BYTES)

__device__ __forceinline__ uint32_t smem_u32(const void* p) {
    uint32_t a;
    asm("{ .reg .u64 t; cvta.to.shared.u64 t, %1; cvt.u32.u64 %0, t; }" : "=r"(a) : "l"(p));
    return a;
}
__device__ __forceinline__ void cp16(uint32_t dst, const void* src) {
    asm volatile("cp.async.cg.shared.global [%0], [%1], 16;" :: "r"(dst), "l"(src) : "memory");
}
__device__ __forceinline__ void mma_bf16(float* d, const uint32_t* a, const uint32_t* b) {
    asm volatile(
        "mma.sync.aligned.m16n8k16.row.col.f32.bf16.bf16.f32 "
        "{%0,%1,%2,%3}, {%4,%5,%6,%7}, {%8,%9}, {%0,%1,%2,%3};"
        : "+f"(d[0]), "+f"(d[1]), "+f"(d[2]), "+f"(d[3])
        : "r"(a[0]), "r"(a[1]), "r"(a[2]), "r"(a[3]), "r"(b[0]), "r"(b[1]));
}

__global__ __launch_bounds__(256, 1) void k_mma(
    const float* __restrict__ A, const __nv_bfloat16* __restrict__ Wh,
    const __nv_bfloat16* __restrict__ Wl, float* __restrict__ C,
    int K, int KPad)
{
    extern __shared__ __align__(16) char smem[];
    const int tid = threadIdx.x;
    const int wid = tid >> 5, lane = tid & 31;
    const int g = lane >> 2, t4 = lane & 3;
    const int wm = wid >> 2, wn = wid & 3;     // warp grid 2(M) x 4(N)
    const int bm = blockIdx.x * 128;
    const int NC = KPad / 32;

    float acc[4][8][4];
#pragma unroll
    for (int mi = 0; mi < 4; mi++)
#pragma unroll
        for (int ni = 0; ni < 8; ni++)
#pragma unroll
            for (int q = 0; q < 4; q++) acc[mi][ni][q] = 0.0f;

    float4 areg[4];

    auto ldA = [&](int c) {
        const int k0 = c * 32;
#pragma unroll
        for (int i = 0; i < 4; i++) {
            int s = i * 256 + tid;
            int r = s >> 3, seg = s & 7;
            int kk = k0 + seg * 4;
            if (kk + 3 < K) {
                areg[i] = *(const float4*)&A[(size_t)(bm + r) * K + kk];
            } else {
                float tmp[4];
#pragma unroll
                for (int j = 0; j < 4; j++)
                    tmp[j] = (kk + j < K) ? A[(size_t)(bm + r) * K + kk + j] : 0.0f;
                areg[i] = make_float4(tmp[0], tmp[1], tmp[2], tmp[3]);
            }
        }
    };
    auto stA = [&](int p) {
        char* base = smem + p * STAGE_BYTES;
#pragma unroll
        for (int i = 0; i < 4; i++) {
            int s = i * 256 + tid;
            int r = s >> 3, seg = s & 7;
            float4 v = areg[i];
            __nv_bfloat16 h0 = __float2bfloat16_rn(v.x), h1 = __float2bfloat16_rn(v.y);
            __nv_bfloat16 h2 = __float2bfloat16_rn(v.z), h3 = __float2bfloat16_rn(v.w);
            __nv_bfloat16 l0 = __float2bfloat16_rn(v.x - __bfloat162float(h0));
            __nv_bfloat16 l1 = __float2bfloat16_rn(v.y - __bfloat162float(h1));
            __nv_bfloat16 l2 = __float2bfloat16_rn(v.z - __bfloat162float(h2));
            __nv_bfloat16 l3 = __float2bfloat16_rn(v.w - __bfloat162float(h3));
            uint2 uh, ul;
            uh.x = ((uint32_t)__bfloat16_as_ushort(h1) << 16) | __bfloat16_as_ushort(h0);
            uh.y = ((uint32_t)__bfloat16_as_ushort(h3) << 16) | __bfloat16_as_ushort(h2);
            ul.x = ((uint32_t)__bfloat16_as_ushort(l1) << 16) | __bfloat16_as_ushort(l0);
            ul.y = ((uint32_t)__bfloat16_as_ushort(l3) << 16) | __bfloat16_as_ushort(l2);
            int off = r * 80 + seg * 8;
            *(uint2*)(base + ST_AH + off) = uh;
            *(uint2*)(base + ST_AL + off) = ul;
        }
    };
    auto cpB = [&](int c, int p) {
        const int k0 = c * 32;
        char* base = smem + p * STAGE_BYTES;
        uint32_t bh = smem_u32(base + ST_BH);
        uint32_t bl = smem_u32(base + ST_BL);
#pragma unroll
        for (int i = 0; i < 4; i++) {
            int s = i * 256 + tid;
            int r = s >> 2, seg = s & 3;
            int off = r * 80 + seg * 16;
            size_t goff = (size_t)r * KPad + k0 + seg * 8;
            cp16(bh + off, Wh + goff);
            cp16(bl + off, Wl + goff);
        }
        asm volatile("cp.async.commit_group;" ::: "memory");
    };

    // prologue
    ldA(0);
    cpB(0, 0);
    stA(0);
    asm volatile("cp.async.wait_group 0;" ::: "memory");
    __syncthreads();

    for (int c = 0; c < NC; c++) {
        const int p = c & 1;
        if (c + 1 < NC) {
            ldA(c + 1);
            cpB(c + 1, p ^ 1);
        }

        const uint16_t* AhS = (const uint16_t*)(smem + p * STAGE_BYTES + ST_AH);
        const uint16_t* AlS = (const uint16_t*)(smem + p * STAGE_BYTES + ST_AL);
        const uint16_t* BhS = (const uint16_t*)(smem + p * STAGE_BYTES + ST_BH);
        const uint16_t* BlS = (const uint16_t*)(smem + p * STAGE_BYTES + ST_BL);
#pragma unroll
        for (int ks = 0; ks < 2; ks++) {
            const int kofs = ks * 16;
            uint32_t bh[8][2], bl[8][2];
#pragma unroll
            for (int ni = 0; ni < 8; ni++) {
                int n0 = wn * 64 + ni * 8 + g;
                int c0 = kofs + 2 * t4;
                bh[ni][0] = *(const uint32_t*)&BhS[n0 * AROWS + c0];
                bh[ni][1] = *(const uint32_t*)&BhS[n0 * AROWS + c0 + 8];
                bl[ni][0] = *(const uint32_t*)&BlS[n0 * AROWS + c0];
                bl[ni][1] = *(const uint32_t*)&BlS[n0 * AROWS + c0 + 8];
            }
#pragma unroll
            for (int mi = 0; mi < 4; mi++) {
                int r0 = wm * 64 + mi * 16 + g;
                int c0 = kofs + 2 * t4;
                uint32_t ah[4], al[4];
                ah[0] = *(const uint32_t*)&AhS[r0 * AROWS + c0];
                ah[1] = *(const uint32_t*)&AhS[(r0 + 8) * AROWS + c0];
                ah[2] = *(const uint32_t*)&AhS[r0 * AROWS + c0 + 8];
                ah[3] = *(const uint32_t*)&AhS[(r0 + 8) * AROWS + c0 + 8];
                al[0] = *(const uint32_t*)&AlS[r0 * AROWS + c0];
                al[1] = *(const uint32_t*)&AlS[(r0 + 8) * AROWS + c0];
                al[2] = *(const uint32_t*)&AlS[r0 * AROWS + c0 + 8];
                al[3] = *(const uint32_t*)&AlS[(r0 + 8) * AROWS + c0 + 8];
#pragma unroll
                for (int ni = 0; ni < 8; ni++) {
                    mma_bf16(acc[mi][ni], ah, bh[ni]);
                    mma_bf16(acc[mi][ni], al, bh[ni]);
                    mma_bf16(acc[mi][ni], ah, bl[ni]);
                }
            }
        }

        if (c + 1 < NC) stA(p ^ 1);
        asm volatile("cp.async.wait_group 0;" ::: "memory");
        __syncthreads();
    }

    // epilogue
#pragma unroll
    for (int mi = 0; mi < 4; mi++) {
        int row = bm + wm * 64 + mi * 16 + g;
#pragma unroll
        for (int ni = 0; ni < 8; ni++) {
            int col = wn * 64 + ni * 8 + 2 * t4;
            float2 v0 = make_float2(acc[mi][ni][0], acc[mi][ni][1]);
            float2 v1 = make_float2(acc[mi][ni][2], acc[mi][ni][3]);
            *(float2*)&C[(size_t)row * 256 + col] = v0;
            *(float2*)&C[(size_t)(row + 8) * 256 + col] = v1;
        }
    }
}

// ======================= layer-5 GEMM (256 -> 16) =======================
__global__ __launch_bounds__(256) void k_gemm16(const float* __restrict__ A,
                                                const float* __restrict__ W)
{
    __shared__ float As[16][256];
    __shared__ float sW[256 * 16];
    int n0 = blockIdx.x * 16;
    int t = threadIdx.x;
#pragma unroll
    for (int i = 0; i < 16; i++) As[i][t] = A[(size_t)(n0 + i) * 256 + t];
#pragma unroll
    for (int i = 0; i < 16; i++) sW[i * 256 + t] = W[i * 256 + t];
    __syncthreads();
    int r = t >> 4, c = t & 15;
    float acc = 0.0f;
#pragma unroll 8
    for (int k = 0; k < 256; k++) acc = fmaf(As[r][k], sW[k * 16 + c], acc);
    g_g16[(size_t)(n0 + r) * 16 + c] = acc;
}

// ======================= GCN aggregation =======================
// HID-wide version: float4 lanes, 4 nodes per 256-thread block
__global__ void k_agg256(const float* __restrict__ gbuf, const float* __restrict__ bias,
                         float* __restrict__ obuf)
{
    int node = blockIdx.x * 4 + (threadIdx.x >> 6);
    int c4 = threadIdx.x & 63;
    const float4* gb = (const float4*)gbuf;
    float4 b4 = ((const float4*)bias)[c4];
    float isd = g_inv_sqrt[node];
    float id  = g_inv_deg[node];
    float4 v = gb[(size_t)node * 64 + c4];
    float4 acc = make_float4(v.x * id, v.y * id, v.z * id, v.w * id);
    int e0 = g_row_ptr[node], e1 = g_row_ptr[node + 1];
#pragma unroll 4
    for (int e = e0; e < e1; e++) {
        int s = g_col[e];
        float w = g_inv_sqrt[s] * isd;
        float4 u = gb[(size_t)s * 64 + c4];
        acc.x = fmaf(u.x, w, acc.x);
        acc.y = fmaf(u.y, w, acc.y);
        acc.z = fmaf(u.z, w, acc.z);
        acc.w = fmaf(u.w, w, acc.w);
    }
    acc.x += b4.x; acc.y += b4.y; acc.z += b4.z; acc.w += b4.w;
    acc.x = acc.x > 0.f ? acc.x : 0.f;
    acc.y = acc.y > 0.f ? acc.y : 0.f;
    acc.z = acc.z > 0.f ? acc.z : 0.f;
    acc.w = acc.w > 0.f ? acc.w : 0.f;
    ((float4*)obuf)[(size_t)node * 64 + c4] = acc;
}

// 16-wide version for layer 5
__global__ void k_agg16(const float* __restrict__ gbuf, const float* __restrict__ bias,
                        float* __restrict__ obuf)
{
    int node = blockIdx.x * 16 + threadIdx.x / 16;
    int c = threadIdx.x % 16;
    float isd = g_inv_sqrt[node];
    float acc = gbuf[(size_t)node * 16 + c] * g_inv_deg[node];
    int e0 = g_row_ptr[node], e1 = g_row_ptr[node + 1];
#pragma unroll 4
    for (int e = e0; e < e1; e++) {
        int s = g_col[e];
        acc = fmaf(gbuf[(size_t)s * 16 + c], g_inv_sqrt[s] * isd, acc);
    }
    acc += bias[c];
    obuf[(size_t)node * 16 + c] = acc > 0.0f ? acc : 0.0f;
}

// ======================= LSTM =======================
// 180 blocks x 256 threads; thread = (node_half, dir, row); 64 iterations of 2 nodes
__global__ void k_lstm_pre(const float* __restrict__ Wih_f, const float* __restrict__ bih_f,
                           const float* __restrict__ bhh_f,
                           const float* __restrict__ Wih_b, const float* __restrict__ bih_b,
                           const float* __restrict__ bhh_b)
{
    int t = threadIdx.x;
    int half = t >> 7;
    int dr = t & 127;
    int d = dr >> 6, r = dr & 63;
    const float* Wp = d ? Wih_b : Wih_f;
    float w[16];
#pragma unroll
    for (int k = 0; k < 16; k++) w[k] = Wp[r * 16 + k];
    float bias = d ? (bih_b[r] + bhh_b[r]) : (bih_f[r] + bhh_f[r]);
    int base = blockIdx.x * 128;
#pragma unroll 4
    for (int it = 0; it < 64; it++) {
        int node = base + it * 2 + half;
        const float* xr = &g_h5[(size_t)node * 16];
        float acc = bias;
#pragma unroll
        for (int k = 0; k < 16; k++) acc = fmaf(xr[k], w[k], acc);
        g_wx[((size_t)d * NN + node) * 64 + r] = acc;
    }
}

__device__ __forceinline__ float sigm_(float x) { return 1.0f / (1.0f + __expf(-x)); }

__global__ void k_lstm_rec(const float* __restrict__ Whh_f, const float* __restrict__ Whh_b)
{
    int wid = blockIdx.x * (blockDim.x / 32) + threadIdx.x / 32;
    int lane = threadIdx.x & 31;
    int d = wid & 1, g = wid >> 1;
    const float* Whh = d ? Whh_b : Whh_f;
    float w0[16], w1[16];
#pragma unroll
    for (int j = 0; j < 16; j++) {
        w0[j] = Whh[lane * 16 + j];
        w1[j] = Whh[(lane + 32) * 16 + j];
    }
    float h = 0.0f, c = 0.0f;
    const float* wx = g_wx + ((size_t)d * NN + (size_t)g * TSEQ) * 64;
    for (int t = 0; t < TSEQ; t++) {
        int tt = d ? (TSEQ - 1 - t) : t;
        const float* wxt = wx + (size_t)tt * 64;
        float g0 = wxt[lane], g1 = wxt[32 + lane];
#pragma unroll
        for (int j = 0; j < 16; j++) {
            float hv = __shfl_sync(0xffffffffu, h, j);
            g0 = fmaf(hv, w0[j], g0);
            g1 = fmaf(hv, w1[j], g1);
        }
        float fk = __shfl_sync(0xffffffffu, g0, (lane & 15) + 16);
        float ok = __shfl_sync(0xffffffffu, g1, (lane & 15) + 16);
        float cn = sigm_(fk) * c + sigm_(g0) * tanhf(g1);
        float hv2 = sigm_(ok) * tanhf(cn);
        c = cn;
        h = hv2;
    }
    if (lane < 16) g_hn[g * 32 + d * 16 + lane] = h;
}

// ======================= final MLP =======================
__global__ void k_mlp(const float* __restrict__ Wm1, const float* __restrict__ bm1,
                      const float* __restrict__ Wm2, const float* __restrict__ bm2,
                      float* __restrict__ out)
{
    __shared__ float hs[32];
    __shared__ float red[128];
    int g = blockIdx.x;
    int t = threadIdx.x;
    if (t < 32) hs[t] = g_hn[g * 32 + t];
    __syncthreads();
    float a = bm1[t];
#pragma unroll
    for (int k = 0; k < 32; k++) a = fmaf(hs[k], Wm1[k * 128 + t], a);
    a = (a > 0.0f ? a : 0.0f) * Wm2[t];
    red[t] = a;
    __syncthreads();
    for (int s = 64; s > 0; s >>= 1) {
        if (t < s) red[t] += red[t + s];
        __syncthreads();
    }
    if (t == 0) out[g] = red[0] + bm2[0];
}

// ======================= launch =======================
static void* symp(const void* sym) {
    void* p = nullptr;
    cudaGetSymbolAddress(&p, sym);
    return p;
}

extern "C" void kernel_launch(void* const* d_in, const int* in_sizes, int n_in,
                              void* d_out, int out_size)
{
    const float* x   = (const float*)d_in[0];
    const int*   ei  = (const int*)d_in[1];
    const int*   src = ei;
    const int*   dst = ei + NE;
    const float* W1 = (const float*)d_in[3],  *b1 = (const float*)d_in[4];
    const float* W2 = (const float*)d_in[5],  *b2 = (const float*)d_in[6];
    const float* W3 = (const float*)d_in[7],  *b3 = (const float*)d_in[8];
    const float* W4 = (const float*)d_in[9],  *b4 = (const float*)d_in[10];
    const float* W5 = (const float*)d_in[11], *b5 = (const float*)d_in[12];
    const float* Wih_f = (const float*)d_in[13], *Whh_f = (const float*)d_in[14];
    const float* bih_f = (const float*)d_in[15], *bhh_f = (const float*)d_in[16];
    const float* Wih_b = (const float*)d_in[17], *Whh_b = (const float*)d_in[18];
    const float* bih_b = (const float*)d_in[19], *bhh_b = (const float*)d_in[20];
    const float* Wm1 = (const float*)d_in[21], *bm1 = (const float*)d_in[22];
    const float* Wm2 = (const float*)d_in[23], *bm2 = (const float*)d_in[24];
    float* out = (float*)d_out;

    float* bufA = (float*)symp(g_bufA);
    float* bufB = (float*)symp(g_bufB);
    const __nv_bfloat16* Wh = (const __nv_bfloat16*)symp(g_Wh);
    const __nv_bfloat16* Wl = (const __nv_bfloat16*)symp(g_Wl);

    cudaFuncSetAttribute(k_mma, cudaFuncAttributeMaxDynamicSharedMemorySize, SMEM_TOTAL);

    dim3 cw1(KP1 / 32, 8), cw2(256 / 32, 8), cwt(32, 8);

    // launches 0..3 — k_mma layer 1 lands on profiled slot (index 3)
    k_zero_deg<<<(NN + 255) / 256, 256>>>();                 // 0
    k_count<<<NE / 256, 256>>>(dst);                         // 1
    k_convW<<<cw1, cwt>>>(W1, 3000, KP1);                    // 2
    k_mma<<<NN / 128, 256, SMEM_TOTAL>>>(x, Wh, Wl, bufA, 3000, KP1);  // 3 <- profiled

    // graph prep (needed before first aggregation)
    k_nodeprep<<<(NN + 255) / 256, 256>>>();
    k_scan1<<<90, 256>>>();
    k_scan2<<<1, 128>>>();
    k_scan3<<<90, 256>>>();
    k_scatter<<<NE / 256, 256>>>(src, dst);

    k_agg256<<<NN / 4, 256>>>(bufA, b1, bufB);

    // layers 2-4 (K=256)
    const float* Ws[3] = {W2, W3, W4};
    const float* bs[3] = {b2, b3, b4};
    for (int l = 0; l < 3; l++) {
        k_convW<<<cw2, cwt>>>(Ws[l], 256, 256);
        k_mma<<<NN / 128, 256, SMEM_TOTAL>>>(bufB, Wh, Wl, bufA, 256, 256);
        k_agg256<<<NN / 4, 256>>>(bufA, bs[l], bufB);
    }
    // layer 5
    k_gemm16<<<NN / 16, 256>>>(bufB, W5);
    k_agg16<<<NN / 16, 256>>>((const float*)symp(g_g16), b5, (float*)symp(g_h5));

    // LSTM
    k_lstm_pre<<<NN / 128, 256>>>(Wih_f, bih_f, bhh_f, Wih_b, bih_b, bhh_b);
    k_lstm_rec<<<32, 128>>>(Whh_f, Whh_b);

    // MLP head
    k_mlp<<<NG, 128>>>(Wm1, bm1, Wm2, bm2, out);
}

// round 5
// speedup vs baseline: 2.0210x; 1.0055x over previous
#include <cuda_runtime.h>
#include <cuda_bf16.h>
#include <math.h>
#include <stdint.h>

#define NN 23040          // nodes
#define NE 368640         // edges
#define NG 64             // graphs
#define TSEQ 360          // nodes per graph
#define HID 256
#define GOUT 16
#define LH 16
#define KP1 3008          // layer-1 K padded to 32

// ======================= device scratch (static) =======================
__device__ int   g_deg[NN];
__device__ float g_inv_sqrt[NN];
__device__ float g_inv_deg[NN];
__device__ int   g_row_ptr[NN + 1];
__device__ int   g_fill[NN];
__device__ int   g_col[NE];
__device__ int   g_excl[NN];
__device__ int   g_bsum[90];
__device__ int   g_boff[128];
__device__ __align__(16) float g_bufA[NN * HID];
__device__ __align__(16) float g_bufB[NN * HID];
__device__ __align__(16) float g_g16[NN * GOUT];
__device__ __align__(16) float g_h5[NN * GOUT];
__device__ float g_wx[2 * NN * 64];
__device__ float g_hn[NG * 32];
// weight hi/lo bf16, layout [256][KP] k-contiguous
__device__ __align__(16) __nv_bfloat16 g_Wh[256 * KP1];
__device__ __align__(16) __nv_bfloat16 g_Wl[256 * KP1];

// ======================= graph prep =======================
__global__ void k_zero_deg() {
    int i = blockIdx.x * 256 + threadIdx.x;
    if (i < NN) g_deg[i] = 0;
}
__global__ void k_count(const int* __restrict__ dst) {
    int e = blockIdx.x * 256 + threadIdx.x;
    if (e < NE) atomicAdd(&g_deg[dst[e]], 1);
}
__global__ void k_nodeprep() {
    int i = blockIdx.x * 256 + threadIdx.x;
    if (i < NN) {
        float d = (float)g_deg[i] + 1.0f;
        g_inv_sqrt[i] = rsqrtf(d);
        g_inv_deg[i]  = 1.0f / d;
    }
}
__global__ void k_scan1() {
    __shared__ int sh[256];
    int t = threadIdx.x;
    int i = blockIdx.x * 256 + t;
    int v = g_deg[i];
    sh[t] = v;
    __syncthreads();
    for (int off = 1; off < 256; off <<= 1) {
        int add = (t >= off) ? sh[t - off] : 0;
        __syncthreads();
        sh[t] += add;
        __syncthreads();
    }
    g_excl[i] = sh[t] - v;
    if (t == 255) g_bsum[blockIdx.x] = sh[t];
}
__global__ void k_scan2() {
    __shared__ int sh[128];
    int t = threadIdx.x;
    int v = (t < 90) ? g_bsum[t] : 0;
    sh[t] = v;
    __syncthreads();
    for (int off = 1; off < 128; off <<= 1) {
        int add = (t >= off) ? sh[t - off] : 0;
        __syncthreads();
        sh[t] += add;
        __syncthreads();
    }
    if (t < 90) g_boff[t] = sh[t] - v;
}
__global__ void k_scan3() {
    int i = blockIdx.x * 256 + threadIdx.x;
    int rp = g_excl[i] + g_boff[blockIdx.x];
    g_row_ptr[i] = rp;
    g_fill[i] = rp;
    if (i == 0) g_row_ptr[NN] = NE;
}
__global__ void k_scatter(const int* __restrict__ src, const int* __restrict__ dst) {
    int e = blockIdx.x * 256 + threadIdx.x;
    if (e < NE) {
        int d = dst[e];
        int p = atomicAdd(&g_fill[d], 1);
        g_col[p] = src[e];
    }
}

// ======================= weight convert (coalesced transpose) =======================
// W fp32 [K][256] -> g_Wh/g_Wl bf16 [256][KPad]
__global__ void k_convW(const float* __restrict__ W, int K, int KPad) {
    __shared__ float tile[32][33];
    int kb = blockIdx.x * 32, nb = blockIdx.y * 32;
    int tx = threadIdx.x, ty = threadIdx.y;   // 32 x 8
#pragma unroll
    for (int i = ty; i < 32; i += 8) {
        int k = kb + i;
        tile[i][tx] = (k < K) ? W[(size_t)k * 256 + nb + tx] : 0.0f;
    }
    __syncthreads();
#pragma unroll
    for (int i = ty; i < 32; i += 8) {
        int n = nb + i, k = kb + tx;
        float v = tile[tx][i];
        __nv_bfloat16 h = __float2bfloat16_rn(v);
        __nv_bfloat16 l = __float2bfloat16_rn(v - __bfloat162float(h));
        size_t o = (size_t)n * KPad + k;
        g_Wh[o] = h;
        g_Wl[o] = l;
    }
}

// ======================= HMMA GEMM: C[M,256] = A[M,K] @ W[K,256] =======================
// bf16 hi/lo split: AhBh + AlBh + AhBl, fp32 accumulate.
// CTA 128x256, 256 threads = 8 warps, warp tile 64x64. Fragments via ldmatrix.x4.
#define AROWS 40               // padded row stride in halves (80 B)
#define ST_AH 0
#define ST_AL 10240
#define ST_BH 20480
#define ST_BL 40960
#define STAGE_BYTES 61440
#define SMEM_TOTAL (2 * STAGE_BYTES)

__device__ __forceinline__ uint32_t smem_u32(const void* p) {
    uint32_t a;
    asm("{ .reg .u64 t; cvta.to.shared.u64 t, %1; cvt.u32.u64 %0, t; }" : "=r"(a) : "l"(p));
    return a;
}
__device__ __forceinline__ void cp16(uint32_t dst, const void* src) {
    asm volatile("cp.async.cg.shared.global [%0], [%1], 16;" :: "r"(dst), "l"(src) : "memory");
}
__device__ __forceinline__ void ldsm4(uint32_t* r, uint32_t addr) {
    asm volatile("ldmatrix.sync.aligned.m8n8.x4.shared.b16 {%0,%1,%2,%3}, [%4];"
        : "=r"(r[0]), "=r"(r[1]), "=r"(r[2]), "=r"(r[3]) : "r"(addr));
}
__device__ __forceinline__ void mma_bf16(float* d, const uint32_t* a, const uint32_t* b) {
    asm volatile(
        "mma.sync.aligned.m16n8k16.row.col.f32.bf16.bf16.f32 "
        "{%0,%1,%2,%3}, {%4,%5,%6,%7}, {%8,%9}, {%0,%1,%2,%3};"
        : "+f"(d[0]), "+f"(d[1]), "+f"(d[2]), "+f"(d[3])
        : "r"(a[0]), "r"(a[1]), "r"(a[2]), "r"(a[3]), "r"(b[0]), "r"(b[1]));
}

__global__ __launch_bounds__(256, 1) void k_mma(
    const float* __restrict__ A, const __nv_bfloat16* __restrict__ Wh,
    const __nv_bfloat16* __restrict__ Wl, float* __restrict__ C,
    int K, int KPad)
{
    extern __shared__ __align__(16) char smem[];
    const int tid = threadIdx.x;
    const int wid = tid >> 5, lane = tid & 31;
    const int g = lane >> 2, t4 = lane & 3;
    const int wm = wid >> 2, wn = wid & 3;     // warp grid 2(M) x 4(N)
    const int bm = blockIdx.x * 128;
    const int NC = KPad / 32;
    const uint32_t smemBase = smem_u32(smem);

    // ldmatrix per-lane row/col offsets
    const int lr = lane & 7, lq = lane >> 3;
    // A matrices: m0 rows+0 k+0 -> a0 ; m1 rows+8 k+0 -> a1 ; m2 rows+0 k+8 -> a2 ; m3 rows+8 k+8
    const int a_row_off = lr + ((lq & 1) << 3);
    const int a_col_off = (lq >> 1) << 3;
    // B matrices: m0 n+0 k+0 -> b0(ni) ; m1 n+0 k+8 -> b1(ni) ; m2 n+8 k+0 -> b0(ni+1) ; m3 n+8 k+8 -> b1(ni+1)
    const int b_row_off = lr + ((lq >> 1) << 3);
    const int b_col_off = (lq & 1) << 3;

    float acc[4][8][4];
#pragma unroll
    for (int mi = 0; mi < 4; mi++)
#pragma unroll
        for (int ni = 0; ni < 8; ni++)
#pragma unroll
            for (int q = 0; q < 4; q++) acc[mi][ni][q] = 0.0f;

    float4 areg[4];

    auto ldA = [&](int c) {
        const int k0 = c * 32;
#pragma unroll
        for (int i = 0; i < 4; i++) {
            int s = i * 256 + tid;
            int r = s >> 3, seg = s & 7;
            int kk = k0 + seg * 4;
            if (kk + 3 < K) {
                areg[i] = *(const float4*)&A[(size_t)(bm + r) * K + kk];
            } else {
                float tmp[4];
#pragma unroll
                for (int j = 0; j < 4; j++)
                    tmp[j] = (kk + j < K) ? A[(size_t)(bm + r) * K + kk + j] : 0.0f;
                areg[i] = make_float4(tmp[0], tmp[1], tmp[2], tmp[3]);
            }
        }
    };
    auto stA = [&](int p) {
        char* base = smem + p * STAGE_BYTES;
#pragma unroll
        for (int i = 0; i < 4; i++) {
            int s = i * 256 + tid;
            int r = s >> 3, seg = s & 7;
            float4 v = areg[i];
            __nv_bfloat16 h0 = __float2bfloat16_rn(v.x), h1 = __float2bfloat16_rn(v.y);
            __nv_bfloat16 h2 = __float2bfloat16_rn(v.z), h3 = __float2bfloat16_rn(v.w);
            __nv_bfloat16 l0 = __float2bfloat16_rn(v.x - __bfloat162float(h0));
            __nv_bfloat16 l1 = __float2bfloat16_rn(v.y - __bfloat162float(h1));
            __nv_bfloat16 l2 = __float2bfloat16_rn(v.z - __bfloat162float(h2));
            __nv_bfloat16 l3 = __float2bfloat16_rn(v.w - __bfloat162float(h3));
            uint2 uh, ul;
            uh.x = ((uint32_t)__bfloat16_as_ushort(h1) << 16) | __bfloat16_as_ushort(h0);
            uh.y = ((uint32_t)__bfloat16_as_ushort(h3) << 16) | __bfloat16_as_ushort(h2);
            ul.x = ((uint32_t)__bfloat16_as_ushort(l1) << 16) | __bfloat16_as_ushort(l0);
            ul.y = ((uint32_t)__bfloat16_as_ushort(l3) << 16) | __bfloat16_as_ushort(l2);
            int off = r * 80 + seg * 8;
            *(uint2*)(base + ST_AH + off) = uh;
            *(uint2*)(base + ST_AL + off) = ul;
        }
    };
    auto cpB = [&](int c, int p) {
        const int k0 = c * 32;
        char* base = smem + p * STAGE_BYTES;
        uint32_t bh = smem_u32(base + ST_BH);
        uint32_t bl = smem_u32(base + ST_BL);
#pragma unroll
        for (int i = 0; i < 4; i++) {
            int s = i * 256 + tid;
            int r = s >> 2, seg = s & 3;
            int off = r * 80 + seg * 16;
            size_t goff = (size_t)r * KPad + k0 + seg * 8;
            cp16(bh + off, Wh + goff);
            cp16(bl + off, Wl + goff);
        }
        asm volatile("cp.async.commit_group;" ::: "memory");
    };

    // prologue
    ldA(0);
    cpB(0, 0);
    stA(0);
    asm volatile("cp.async.wait_group 0;" ::: "memory");
    __syncthreads();

    for (int c = 0; c < NC; c++) {
        const int p = c & 1;
        if (c + 1 < NC) {
            ldA(c + 1);
            cpB(c + 1, p ^ 1);
        }

        const uint32_t stAh = smemBase + p * STAGE_BYTES + ST_AH;
        const uint32_t stAl = smemBase + p * STAGE_BYTES + ST_AL;
        const uint32_t stBh = smemBase + p * STAGE_BYTES + ST_BH;
        const uint32_t stBl = smemBase + p * STAGE_BYTES + ST_BL;
#pragma unroll
        for (int ks = 0; ks < 2; ks++) {
            const int kofs = ks * 16;
            // B fragments: 4 ldmatrix.x4 per hi/lo, each covers ni pair (2j, 2j+1)
            uint32_t bh[8][2], bl[8][2];
#pragma unroll
            for (int j = 0; j < 4; j++) {
                int row = wn * 64 + j * 16 + b_row_off;
                int col = kofs + b_col_off;
                uint32_t r4[4];
                ldsm4(r4, stBh + ((row * AROWS + col) << 1));
                bh[2 * j][0] = r4[0]; bh[2 * j][1] = r4[1];
                bh[2 * j + 1][0] = r4[2]; bh[2 * j + 1][1] = r4[3];
                ldsm4(r4, stBl + ((row * AROWS + col) << 1));
                bl[2 * j][0] = r4[0]; bl[2 * j][1] = r4[1];
                bl[2 * j + 1][0] = r4[2]; bl[2 * j + 1][1] = r4[3];
            }
#pragma unroll
            for (int mi = 0; mi < 4; mi++) {
                int row = wm * 64 + mi * 16 + a_row_off;
                int col = kofs + a_col_off;
                uint32_t ah[4], al[4];
                ldsm4(ah, stAh + ((row * AROWS + col) << 1));
                ldsm4(al, stAl + ((row * AROWS + col) << 1));
#pragma unroll
                for (int ni = 0; ni < 8; ni++) {
                    mma_bf16(acc[mi][ni], ah, bh[ni]);
                    mma_bf16(acc[mi][ni], al, bh[ni]);
                    mma_bf16(acc[mi][ni], ah, bl[ni]);
                }
            }
        }

        if (c + 1 < NC) stA(p ^ 1);
        asm volatile("cp.async.wait_group 0;" ::: "memory");
        __syncthreads();
    }

    // epilogue
#pragma unroll
    for (int mi = 0; mi < 4; mi++) {
        int row = bm + wm * 64 + mi * 16 + g;
#pragma unroll
        for (int ni = 0; ni < 8; ni++) {
            int col = wn * 64 + ni * 8 + 2 * t4;
            float2 v0 = make_float2(acc[mi][ni][0], acc[mi][ni][1]);
            float2 v1 = make_float2(acc[mi][ni][2], acc[mi][ni][3]);
            *(float2*)&C[(size_t)row * 256 + col] = v0;
            *(float2*)&C[(size_t)(row + 8) * 256 + col] = v1;
        }
    }
}

// ======================= layer-5 GEMM (256 -> 16) =======================
__global__ __launch_bounds__(256) void k_gemm16(const float* __restrict__ A,
                                                const float* __restrict__ W)
{
    __shared__ float As[16][256];
    __shared__ float sW[256 * 16];
    int n0 = blockIdx.x * 16;
    int t = threadIdx.x;
#pragma unroll
    for (int i = 0; i < 16; i++) As[i][t] = A[(size_t)(n0 + i) * 256 + t];
#pragma unroll
    for (int i = 0; i < 16; i++) sW[i * 256 + t] = W[i * 256 + t];
    __syncthreads();
    int r = t >> 4, c = t & 15;
    float acc = 0.0f;
#pragma unroll 8
    for (int k = 0; k < 256; k++) acc = fmaf(As[r][k], sW[k * 16 + c], acc);
    g_g16[(size_t)(n0 + r) * 16 + c] = acc;
}

// ======================= GCN aggregation =======================
__global__ void k_agg256(const float* __restrict__ gbuf, const float* __restrict__ bias,
                         float* __restrict__ obuf)
{
    int node = blockIdx.x * 4 + (threadIdx.x >> 6);
    int c4 = threadIdx.x & 63;
    const float4* gb = (const float4*)gbuf;
    float4 b4 = ((const float4*)bias)[c4];
    float isd = g_inv_sqrt[node];
    float id  = g_inv_deg[node];
    float4 v = gb[(size_t)node * 64 + c4];
    float4 acc = make_float4(v.x * id, v.y * id, v.z * id, v.w * id);
    int e0 = g_row_ptr[node], e1 = g_row_ptr[node + 1];
#pragma unroll 4
    for (int e = e0; e < e1; e++) {
        int s = g_col[e];
        float w = g_inv_sqrt[s] * isd;
        float4 u = gb[(size_t)s * 64 + c4];
        acc.x = fmaf(u.x, w, acc.x);
        acc.y = fmaf(u.y, w, acc.y);
        acc.z = fmaf(u.z, w, acc.z);
        acc.w = fmaf(u.w, w, acc.w);
    }
    acc.x += b4.x; acc.y += b4.y; acc.z += b4.z; acc.w += b4.w;
    acc.x = acc.x > 0.f ? acc.x : 0.f;
    acc.y = acc.y > 0.f ? acc.y : 0.f;
    acc.z = acc.z > 0.f ? acc.z : 0.f;
    acc.w = acc.w > 0.f ? acc.w : 0.f;
    ((float4*)obuf)[(size_t)node * 64 + c4] = acc;
}

__global__ void k_agg16(const float* __restrict__ gbuf, const float* __restrict__ bias,
                        float* __restrict__ obuf)
{
    int node = blockIdx.x * 16 + threadIdx.x / 16;
    int c = threadIdx.x % 16;
    float isd = g_inv_sqrt[node];
    float acc = gbuf[(size_t)node * 16 + c] * g_inv_deg[node];
    int e0 = g_row_ptr[node], e1 = g_row_ptr[node + 1];
#pragma unroll 4
    for (int e = e0; e < e1; e++) {
        int s = g_col[e];
        acc = fmaf(gbuf[(size_t)s * 16 + c], g_inv_sqrt[s] * isd, acc);
    }
    acc += bias[c];
    obuf[(size_t)node * 16 + c] = acc > 0.0f ? acc : 0.0f;
}

// ======================= LSTM =======================
__global__ void k_lstm_pre(const float* __restrict__ Wih_f, const float* __restrict__ bih_f,
                           const float* __restrict__ bhh_f,
                           const float* __restrict__ Wih_b, const float* __restrict__ bih_b,
                           const float* __restrict__ bhh_b)
{
    int t = threadIdx.x;
    int half = t >> 7;
    int dr = t & 127;
    int d = dr >> 6, r = dr & 63;
    const float* Wp = d ? Wih_b : Wih_f;
    float w[16];
#pragma unroll
    for (int k = 0; k < 16; k++) w[k] = Wp[r * 16 + k];
    float bias = d ? (bih_b[r] + bhh_b[r]) : (bih_f[r] + bhh_f[r]);
    int base = blockIdx.x * 128;
#pragma unroll 4
    for (int it = 0; it < 64; it++) {
        int node = base + it * 2 + half;
        const float* xr = &g_h5[(size_t)node * 16];
        float acc = bias;
#pragma unroll
        for (int k = 0; k < 16; k++) acc = fmaf(xr[k], w[k], acc);
        g_wx[((size_t)d * NN + node) * 64 + r] = acc;
    }
}

__device__ __forceinline__ float sigm_(float x) { return 1.0f / (1.0f + __expf(-x)); }

__global__ void k_lstm_rec(const float* __restrict__ Whh_f, const float* __restrict__ Whh_b)
{
    int wid = blockIdx.x * (blockDim.x / 32) + threadIdx.x / 32;
    int lane = threadIdx.x & 31;
    int d = wid & 1, g = wid >> 1;
    const float* Whh = d ? Whh_b : Whh_f;
    float w0[16], w1[16];
#pragma unroll
    for (int j = 0; j < 16; j++) {
        w0[j] = Whh[lane * 16 + j];
        w1[j] = Whh[(lane + 32) * 16 + j];
    }
    float h = 0.0f, c = 0.0f;
    const float* wx = g_wx + ((size_t)d * NN + (size_t)g * TSEQ) * 64;
    for (int t = 0; t < TSEQ; t++) {
        int tt = d ? (TSEQ - 1 - t) : t;
        const float* wxt = wx + (size_t)tt * 64;
        float g0 = wxt[lane], g1 = wxt[32 + lane];
#pragma unroll
        for (int j = 0; j < 16; j++) {
            float hv = __shfl_sync(0xffffffffu, h, j);
            g0 = fmaf(hv, w0[j], g0);
            g1 = fmaf(hv, w1[j], g1);
        }
        float fk = __shfl_sync(0xffffffffu, g0, (lane & 15) + 16);
        float ok = __shfl_sync(0xffffffffu, g1, (lane & 15) + 16);
        float cn = sigm_(fk) * c + sigm_(g0) * tanhf(g1);
        float hv2 = sigm_(ok) * tanhf(cn);
        c = cn;
        h = hv2;
    }
    if (lane < 16) g_hn[g * 32 + d * 16 + lane] = h;
}

// ======================= final MLP =======================
__global__ void k_mlp(const float* __restrict__ Wm1, const float* __restrict__ bm1,
                      const float* __restrict__ Wm2, const float* __restrict__ bm2,
                      float* __restrict__ out)
{
    __shared__ float hs[32];
    __shared__ float red[128];
    int g = blockIdx.x;
    int t = threadIdx.x;
    if (t < 32) hs[t] = g_hn[g * 32 + t];
    __syncthreads();
    float a = bm1[t];
#pragma unroll
    for (int k = 0; k < 32; k++) a = fmaf(hs[k], Wm1[k * 128 + t], a);
    a = (a > 0.0f ? a : 0.0f) * Wm2[t];
    red[t] = a;
    __syncthreads();
    for (int s = 64; s > 0; s >>= 1) {
        if (t < s) red[t] += red[t + s];
        __syncthreads();
    }
    if (t == 0) out[g] = red[0] + bm2[0];
}

// ======================= launch =======================
static void* symp(const void* sym) {
    void* p = nullptr;
    cudaGetSymbolAddress(&p, sym);
    return p;
}

extern "C" void kernel_launch(void* const* d_in, const int* in_sizes, int n_in,
                              void* d_out, int out_size)
{
    const float* x   = (const float*)d_in[0];
    const int*   ei  = (const int*)d_in[1];
    const int*   src = ei;
    const int*   dst = ei + NE;
    const float* W1 = (const float*)d_in[3],  *b1 = (const float*)d_in[4];
    const float* W2 = (const float*)d_in[5],  *b2 = (const float*)d_in[6];
    const float* W3 = (const float*)d_in[7],  *b3 = (const float*)d_in[8];
    const float* W4 = (const float*)d_in[9],  *b4 = (const float*)d_in[10];
    const float* W5 = (const float*)d_in[11], *b5 = (const float*)d_in[12];
    const float* Wih_f = (const float*)d_in[13], *Whh_f = (const float*)d_in[14];
    const float* bih_f = (const float*)d_in[15], *bhh_f = (const float*)d_in[16];
    const float* Wih_b = (const float*)d_in[17], *Whh_b = (const float*)d_in[18];
    const float* bih_b = (const float*)d_in[19], *bhh_b = (const float*)d_in[20];
    const float* Wm1 = (const float*)d_in[21], *bm1 = (const float*)d_in[22];
    const float* Wm2 = (const float*)d_in[23], *bm2 = (const float*)d_in[24];
    float* out = (float*)d_out;

    float* bufA = (float*)symp(g_bufA);
    float* bufB = (float*)symp(g_bufB);
    const __nv_bfloat16* Wh = (const __nv_bfloat16*)symp(g_Wh);
    const __nv_bfloat16* Wl = (const __nv_bfloat16*)symp(g_Wl);

    cudaFuncSetAttribute(k_mma, cudaFuncAttributeMaxDynamicSharedMemorySize, SMEM_TOTAL);

    dim3 cw1(KP1 / 32, 8), cw2(256 / 32, 8), cwt(32, 8);

    // launches 0..3 — k_mma layer 1 lands on profiled slot (index 3)
    k_zero_deg<<<(NN + 255) / 256, 256>>>();                 // 0
    k_count<<<NE / 256, 256>>>(dst);                         // 1
    k_convW<<<cw1, cwt>>>(W1, 3000, KP1);                    // 2
    k_mma<<<NN / 128, 256, SMEM_TOTAL>>>(x, Wh, Wl, bufA, 3000, KP1);  // 3 <- profiled

    // graph prep (needed before first aggregation)
    k_nodeprep<<<(NN + 255) / 256, 256>>>();
    k_scan1<<<90, 256>>>();
    k_scan2<<<1, 128>>>();
    k_scan3<<<90, 256>>>();
    k_scatter<<<NE / 256, 256>>>(src, dst);

    k_agg256<<<NN / 4, 256>>>(bufA, b1, bufB);

    // layers 2-4 (K=256)
    const float* Ws[3] = {W2, W3, W4};
    const float* bs[3] = {b2, b3, b4};
    for (int l = 0; l < 3; l++) {
        k_convW<<<cw2, cwt>>>(Ws[l], 256, 256);
        k_mma<<<NN / 128, 256, SMEM_TOTAL>>>(bufB, Wh, Wl, bufA, 256, 256);
        k_agg256<<<NN / 4, 256>>>(bufA, bs[l], bufB);
    }
    // layer 5
    k_gemm16<<<NN / 16, 256>>>(bufB, W5);
    k_agg16<<<NN / 16, 256>>>((const float*)symp(g_g16), b5, (float*)symp(g_h5));

    // LSTM
    k_lstm_pre<<<NN / 128, 256>>>(Wih_f, bih_f, bhh_f, Wih_b, bih_b, bhh_b);
    k_lstm_rec<<<32, 128>>>(Whh_f, Whh_b);

    // MLP head
    k_mlp<<<NG, 128>>>(Wm1, bm1, Wm2, bm2, out);
}

// round 6
// speedup vs baseline: 2.6996x; 1.3357x over previous
#include <cuda_runtime.h>
#include <cuda_bf16.h>
#include <math.h>
#include <stdint.h>

#define NN 23040          // nodes
#define NE 368640         // edges
#define NG 64             // graphs
#define TSEQ 360          // nodes per graph
#define HID 256
#define GOUT 16
#define LH 16
#define KP1 3008          // layer-1 K padded to 32

// ======================= device scratch (static) =======================
__device__ int   g_deg[NN];
__device__ float g_inv_sqrt[NN];
__device__ float g_inv_deg[NN];
__device__ int   g_row_ptr[NN + 1];
__device__ int   g_fill[NN];
__device__ int   g_col[NE];
__device__ int   g_excl[NN];
__device__ int   g_bsum[90];
__device__ int   g_boff[128];
__device__ __align__(16) float g_bufA[NN * HID];
__device__ __align__(16) float g_bufB[NN * HID];
__device__ __align__(16) float g_g16[NN * GOUT];
__device__ __align__(16) float g_h5[NN * GOUT];
__device__ float g_wx[2 * NN * 64];
__device__ float g_hn[NG * 32];
// weight hi/lo bf16, layout [256][KP] k-contiguous
__device__ __align__(16) __nv_bfloat16 g_Wh[256 * KP1];
__device__ __align__(16) __nv_bfloat16 g_Wl[256 * KP1];

// ======================= graph prep =======================
__global__ void k_zero_deg() {
    int i = blockIdx.x * 256 + threadIdx.x;
    if (i < NN) g_deg[i] = 0;
}
__global__ void k_count(const int* __restrict__ dst) {
    int e = blockIdx.x * 256 + threadIdx.x;
    if (e < NE) atomicAdd(&g_deg[dst[e]], 1);
}
__global__ void k_nodeprep() {
    int i = blockIdx.x * 256 + threadIdx.x;
    if (i < NN) {
        float d = (float)g_deg[i] + 1.0f;
        g_inv_sqrt[i] = rsqrtf(d);
        g_inv_deg[i]  = 1.0f / d;
    }
}
__global__ void k_scan1() {
    __shared__ int sh[256];
    int t = threadIdx.x;
    int i = blockIdx.x * 256 + t;
    int v = g_deg[i];
    sh[t] = v;
    __syncthreads();
    for (int off = 1; off < 256; off <<= 1) {
        int add = (t >= off) ? sh[t - off] : 0;
        __syncthreads();
        sh[t] += add;
        __syncthreads();
    }
    g_excl[i] = sh[t] - v;
    if (t == 255) g_bsum[blockIdx.x] = sh[t];
}
__global__ void k_scan2() {
    __shared__ int sh[128];
    int t = threadIdx.x;
    int v = (t < 90) ? g_bsum[t] : 0;
    sh[t] = v;
    __syncthreads();
    for (int off = 1; off < 128; off <<= 1) {
        int add = (t >= off) ? sh[t - off] : 0;
        __syncthreads();
        sh[t] += add;
        __syncthreads();
    }
    if (t < 90) g_boff[t] = sh[t] - v;
}
__global__ void k_scan3() {
    int i = blockIdx.x * 256 + threadIdx.x;
    int rp = g_excl[i] + g_boff[blockIdx.x];
    g_row_ptr[i] = rp;
    g_fill[i] = rp;
    if (i == 0) g_row_ptr[NN] = NE;
}
__global__ void k_scatter(const int* __restrict__ src, const int* __restrict__ dst) {
    int e = blockIdx.x * 256 + threadIdx.x;
    if (e < NE) {
        int d = dst[e];
        int p = atomicAdd(&g_fill[d], 1);
        g_col[p] = src[e];
    }
}

// ======================= weight convert (coalesced transpose) =======================
// W fp32 [K][256] -> g_Wh/g_Wl bf16 [256][KPad]
__global__ void k_convW(const float* __restrict__ W, int K, int KPad) {
    __shared__ float tile[32][33];
    int kb = blockIdx.x * 32, nb = blockIdx.y * 32;
    int tx = threadIdx.x, ty = threadIdx.y;   // 32 x 8
#pragma unroll
    for (int i = ty; i < 32; i += 8) {
        int k = kb + i;
        tile[i][tx] = (k < K) ? W[(size_t)k * 256 + nb + tx] : 0.0f;
    }
    __syncthreads();
#pragma unroll
    for (int i = ty; i < 32; i += 8) {
        int n = nb + i, k = kb + tx;
        float v = tile[tx][i];
        __nv_bfloat16 h = __float2bfloat16_rn(v);
        __nv_bfloat16 l = __float2bfloat16_rn(v - __bfloat162float(h));
        size_t o = (size_t)n * KPad + k;
        g_Wh[o] = h;
        g_Wl[o] = l;
    }
}

// ======================= HMMA GEMM: C[M,256] = A[M,K] @ W[K,256] =======================
// bf16 hi/lo split: AhBh + AlBh + AhBl, fp32 accumulate.
// CTA 160x256, 512 threads = 16 warps (2M x 8N), warp tile 80x32. grid = 144 = one wave.
#define AROWS 40               // padded row stride in halves (80 B)
#define MT 160                 // CTA M tile
#define ST_AH 0
#define ST_AL 12800
#define ST_BH 25600
#define ST_BL 46080
#define STAGE_BYTES 66560
#define SMEM_TOTAL (2 * STAGE_BYTES)

__device__ __forceinline__ uint32_t smem_u32(const void* p) {
    uint32_t a;
    asm("{ .reg .u64 t; cvta.to.shared.u64 t, %1; cvt.u32.u64 %0, t; }" : "=r"(a) : "l"(p));
    return a;
}
__device__ __forceinline__ void cp16(uint32_t dst, const void* src) {
    asm volatile("cp.async.cg.shared.global [%0], [%1], 16;" :: "r"(dst), "l"(src) : "memory");
}
__device__ __forceinline__ void ldsm4(uint32_t* r, uint32_t addr) {
    asm volatile("ldmatrix.sync.aligned.m8n8.x4.shared.b16 {%0,%1,%2,%3}, [%4];"
        : "=r"(r[0]), "=r"(r[1]), "=r"(r[2]), "=r"(r[3]) : "r"(addr));
}
__device__ __forceinline__ void mma_bf16(float* d, const uint32_t* a, const uint32_t* b) {
    asm volatile(
        "mma.sync.aligned.m16n8k16.row.col.f32.bf16.bf16.f32 "
        "{%0,%1,%2,%3}, {%4,%5,%6,%7}, {%8,%9}, {%0,%1,%2,%3};"
        : "+f"(d[0]), "+f"(d[1]), "+f"(d[2]), "+f"(d[3])
        : "r"(a[0]), "r"(a[1]), "r"(a[2]), "r"(a[3]), "r"(b[0]), "r"(b[1]));
}

__global__ __launch_bounds__(512, 1) void k_mma(
    const float* __restrict__ A, const __nv_bfloat16* __restrict__ Wh,
    const __nv_bfloat16* __restrict__ Wl, float* __restrict__ C,
    int K, int KPad)
{
    extern __shared__ __align__(16) char smem[];
    const int tid = threadIdx.x;
    const int wid = tid >> 5, lane = tid & 31;
    const int g = lane >> 2, t4 = lane & 3;
    const int wm = wid >> 3, wn = wid & 7;     // warp grid 2(M) x 8(N)
    const int bm = blockIdx.x * MT;
    const int NC = KPad / 32;
    const uint32_t smemBase = smem_u32(smem);

    // ldmatrix per-lane row/col offsets (validated in R5)
    const int lr = lane & 7, lq = lane >> 3;
    const int a_row_off = lr + ((lq & 1) << 3);
    const int a_col_off = (lq >> 1) << 3;
    const int b_row_off = lr + ((lq >> 1) << 3);
    const int b_col_off = (lq & 1) << 3;

    float acc[5][4][4];
#pragma unroll
    for (int mi = 0; mi < 5; mi++)
#pragma unroll
        for (int ni = 0; ni < 4; ni++)
#pragma unroll
            for (int q = 0; q < 4; q++) acc[mi][ni][q] = 0.0f;

    // A chunk = 160 rows x 8 float4 = 1280 float4; 512 threads -> <=3 each
    float4 areg[3];

    auto ldA = [&](int c) {
        const int k0 = c * 32;
#pragma unroll
        for (int i = 0; i < 3; i++) {
            int s = i * 512 + tid;
            if (s < MT * 8) {
                int r = s >> 3, seg = s & 7;
                int kk = k0 + seg * 4;
                if (kk + 3 < K) {
                    areg[i] = *(const float4*)&A[(size_t)(bm + r) * K + kk];
                } else {
                    float tmp[4];
#pragma unroll
                    for (int j = 0; j < 4; j++)
                        tmp[j] = (kk + j < K) ? A[(size_t)(bm + r) * K + kk + j] : 0.0f;
                    areg[i] = make_float4(tmp[0], tmp[1], tmp[2], tmp[3]);
                }
            }
        }
    };
    auto stA = [&](int p) {
        char* base = smem + p * STAGE_BYTES;
#pragma unroll
        for (int i = 0; i < 3; i++) {
            int s = i * 512 + tid;
            if (s < MT * 8) {
                int r = s >> 3, seg = s & 7;
                float4 v = areg[i];
                __nv_bfloat16 h0 = __float2bfloat16_rn(v.x), h1 = __float2bfloat16_rn(v.y);
                __nv_bfloat16 h2 = __float2bfloat16_rn(v.z), h3 = __float2bfloat16_rn(v.w);
                __nv_bfloat16 l0 = __float2bfloat16_rn(v.x - __bfloat162float(h0));
                __nv_bfloat16 l1 = __float2bfloat16_rn(v.y - __bfloat162float(h1));
                __nv_bfloat16 l2 = __float2bfloat16_rn(v.z - __bfloat162float(h2));
                __nv_bfloat16 l3 = __float2bfloat16_rn(v.w - __bfloat162float(h3));
                uint2 uh, ul;
                uh.x = ((uint32_t)__bfloat16_as_ushort(h1) << 16) | __bfloat16_as_ushort(h0);
                uh.y = ((uint32_t)__bfloat16_as_ushort(h3) << 16) | __bfloat16_as_ushort(h2);
                ul.x = ((uint32_t)__bfloat16_as_ushort(l1) << 16) | __bfloat16_as_ushort(l0);
                ul.y = ((uint32_t)__bfloat16_as_ushort(l3) << 16) | __bfloat16_as_ushort(l2);
                int off = r * 80 + seg * 8;
                *(uint2*)(base + ST_AH + off) = uh;
                *(uint2*)(base + ST_AL + off) = ul;
            }
        }
    };
    auto cpB = [&](int c, int p) {
        const int k0 = c * 32;
        char* base = smem + p * STAGE_BYTES;
        uint32_t bh = smem_u32(base + ST_BH);
        uint32_t bl = smem_u32(base + ST_BL);
#pragma unroll
        for (int i = 0; i < 2; i++) {
            int s = i * 512 + tid;
            int r = s >> 2, seg = s & 3;
            int off = r * 80 + seg * 16;
            size_t goff = (size_t)r * KPad + k0 + seg * 8;
            cp16(bh + off, Wh + goff);
            cp16(bl + off, Wl + goff);
        }
        asm volatile("cp.async.commit_group;" ::: "memory");
    };

    // prologue
    ldA(0);
    cpB(0, 0);
    stA(0);
    asm volatile("cp.async.wait_group 0;" ::: "memory");
    __syncthreads();

    for (int c = 0; c < NC; c++) {
        const int p = c & 1;
        if (c + 1 < NC) {
            ldA(c + 1);
            cpB(c + 1, p ^ 1);
        }

        const uint32_t stAh = smemBase + p * STAGE_BYTES + ST_AH;
        const uint32_t stAl = smemBase + p * STAGE_BYTES + ST_AL;
        const uint32_t stBh = smemBase + p * STAGE_BYTES + ST_BH;
        const uint32_t stBl = smemBase + p * STAGE_BYTES + ST_BL;
#pragma unroll
        for (int ks = 0; ks < 2; ks++) {
            const int kofs = ks * 16;
            uint32_t bh[4][2], bl[4][2];
#pragma unroll
            for (int j = 0; j < 2; j++) {
                int row = wn * 32 + j * 16 + b_row_off;
                int col = kofs + b_col_off;
                uint32_t r4[4];
                ldsm4(r4, stBh + ((row * AROWS + col) << 1));
                bh[2 * j][0] = r4[0]; bh[2 * j][1] = r4[1];
                bh[2 * j + 1][0] = r4[2]; bh[2 * j + 1][1] = r4[3];
                ldsm4(r4, stBl + ((row * AROWS + col) << 1));
                bl[2 * j][0] = r4[0]; bl[2 * j][1] = r4[1];
                bl[2 * j + 1][0] = r4[2]; bl[2 * j + 1][1] = r4[3];
            }
#pragma unroll
            for (int mi = 0; mi < 5; mi++) {
                int row = wm * 80 + mi * 16 + a_row_off;
                int col = kofs + a_col_off;
                uint32_t ah[4], al[4];
                ldsm4(ah, stAh + ((row * AROWS + col) << 1));
                ldsm4(al, stAl + ((row * AROWS + col) << 1));
#pragma unroll
                for (int ni = 0; ni < 4; ni++) {
                    mma_bf16(acc[mi][ni], ah, bh[ni]);
                    mma_bf16(acc[mi][ni], al, bh[ni]);
                    mma_bf16(acc[mi][ni], ah, bl[ni]);
                }
            }
        }

        if (c + 1 < NC) stA(p ^ 1);
        asm volatile("cp.async.wait_group 0;" ::: "memory");
        __syncthreads();
    }

    // epilogue
#pragma unroll
    for (int mi = 0; mi < 5; mi++) {
        int row = bm + wm * 80 + mi * 16 + g;
#pragma unroll
        for (int ni = 0; ni < 4; ni++) {
            int col = wn * 32 + ni * 8 + 2 * t4;
            float2 v0 = make_float2(acc[mi][ni][0], acc[mi][ni][1]);
            float2 v1 = make_float2(acc[mi][ni][2], acc[mi][ni][3]);
            *(float2*)&C[(size_t)row * 256 + col] = v0;
            *(float2*)&C[(size_t)(row + 8) * 256 + col] = v1;
        }
    }
}

// ======================= layer-5 GEMM (256 -> 16) =======================
__global__ __launch_bounds__(256) void k_gemm16(const float* __restrict__ A,
                                                const float* __restrict__ W)
{
    __shared__ float As[16][256];
    __shared__ float sW[256 * 16];
    int n0 = blockIdx.x * 16;
    int t = threadIdx.x;
#pragma unroll
    for (int i = 0; i < 16; i++) As[i][t] = A[(size_t)(n0 + i) * 256 + t];
#pragma unroll
    for (int i = 0; i < 16; i++) sW[i * 256 + t] = W[i * 256 + t];
    __syncthreads();
    int r = t >> 4, c = t & 15;
    float acc = 0.0f;
#pragma unroll 8
    for (int k = 0; k < 256; k++) acc = fmaf(As[r][k], sW[k * 16 + c], acc);
    g_g16[(size_t)(n0 + r) * 16 + c] = acc;
}

// ======================= GCN aggregation =======================
__global__ void k_agg256(const float* __restrict__ gbuf, const float* __restrict__ bias,
                         float* __restrict__ obuf)
{
    int node = blockIdx.x * 4 + (threadIdx.x >> 6);
    int c4 = threadIdx.x & 63;
    const float4* gb = (const float4*)gbuf;
    float4 b4 = ((const float4*)bias)[c4];
    float isd = g_inv_sqrt[node];
    float id  = g_inv_deg[node];
    float4 v = gb[(size_t)node * 64 + c4];
    float4 acc = make_float4(v.x * id, v.y * id, v.z * id, v.w * id);
    int e0 = g_row_ptr[node], e1 = g_row_ptr[node + 1];
#pragma unroll 4
    for (int e = e0; e < e1; e++) {
        int s = g_col[e];
        float w = g_inv_sqrt[s] * isd;
        float4 u = gb[(size_t)s * 64 + c4];
        acc.x = fmaf(u.x, w, acc.x);
        acc.y = fmaf(u.y, w, acc.y);
        acc.z = fmaf(u.z, w, acc.z);
        acc.w = fmaf(u.w, w, acc.w);
    }
    acc.x += b4.x; acc.y += b4.y; acc.z += b4.z; acc.w += b4.w;
    acc.x = acc.x > 0.f ? acc.x : 0.f;
    acc.y = acc.y > 0.f ? acc.y : 0.f;
    acc.z = acc.z > 0.f ? acc.z : 0.f;
    acc.w = acc.w > 0.f ? acc.w : 0.f;
    ((float4*)obuf)[(size_t)node * 64 + c4] = acc;
}

__global__ void k_agg16(const float* __restrict__ gbuf, const float* __restrict__ bias,
                        float* __restrict__ obuf)
{
    int node = blockIdx.x * 16 + threadIdx.x / 16;
    int c = threadIdx.x % 16;
    float isd = g_inv_sqrt[node];
    float acc = gbuf[(size_t)node * 16 + c] * g_inv_deg[node];
    int e0 = g_row_ptr[node], e1 = g_row_ptr[node + 1];
#pragma unroll 4
    for (int e = e0; e < e1; e++) {
        int s = g_col[e];
        acc = fmaf(gbuf[(size_t)s * 16 + c], g_inv_sqrt[s] * isd, acc);
    }
    acc += bias[c];
    obuf[(size_t)node * 16 + c] = acc > 0.0f ? acc : 0.0f;
}

// ======================= LSTM =======================
__global__ void k_lstm_pre(const float* __restrict__ Wih_f, const float* __restrict__ bih_f,
                           const float* __restrict__ bhh_f,
                           const float* __restrict__ Wih_b, const float* __restrict__ bih_b,
                           const float* __restrict__ bhh_b)
{
    int t = threadIdx.x;
    int half = t >> 7;
    int dr = t & 127;
    int d = dr >> 6, r = dr & 63;
    const float* Wp = d ? Wih_b : Wih_f;
    float w[16];
#pragma unroll
    for (int k = 0; k < 16; k++) w[k] = Wp[r * 16 + k];
    float bias = d ? (bih_b[r] + bhh_b[r]) : (bih_f[r] + bhh_f[r]);
    int base = blockIdx.x * 128;
#pragma unroll 4
    for (int it = 0; it < 64; it++) {
        int node = base + it * 2 + half;
        const float* xr = &g_h5[(size_t)node * 16];
        float acc = bias;
#pragma unroll
        for (int k = 0; k < 16; k++) acc = fmaf(xr[k], w[k], acc);
        g_wx[((size_t)d * NN + node) * 64 + r] = acc;
    }
}

__device__ __forceinline__ float sigm_(float x) { return 1.0f / (1.0f + __expf(-x)); }

__global__ void k_lstm_rec(const float* __restrict__ Whh_f, const float* __restrict__ Whh_b)
{
    int wid = blockIdx.x * (blockDim.x / 32) + threadIdx.x / 32;
    int lane = threadIdx.x & 31;
    int d = wid & 1, g = wid >> 1;
    const float* Whh = d ? Whh_b : Whh_f;
    float w0[16], w1[16];
#pragma unroll
    for (int j = 0; j < 16; j++) {
        w0[j] = Whh[lane * 16 + j];
        w1[j] = Whh[(lane + 32) * 16 + j];
    }
    float h = 0.0f, c = 0.0f;
    const float* wx = g_wx + ((size_t)d * NN + (size_t)g * TSEQ) * 64;
    for (int t = 0; t < TSEQ; t++) {
        int tt = d ? (TSEQ - 1 - t) : t;
        const float* wxt = wx + (size_t)tt * 64;
        float g0 = wxt[lane], g1 = wxt[32 + lane];
#pragma unroll
        for (int j = 0; j < 16; j++) {
            float hv = __shfl_sync(0xffffffffu, h, j);
            g0 = fmaf(hv, w0[j], g0);
            g1 = fmaf(hv, w1[j], g1);
        }
        float fk = __shfl_sync(0xffffffffu, g0, (lane & 15) + 16);
        float ok = __shfl_sync(0xffffffffu, g1, (lane & 15) + 16);
        float cn = sigm_(fk) * c + sigm_(g0) * tanhf(g1);
        float hv2 = sigm_(ok) * tanhf(cn);
        c = cn;
        h = hv2;
    }
    if (lane < 16) g_hn[g * 32 + d * 16 + lane] = h;
}

// ======================= final MLP =======================
__global__ void k_mlp(const float* __restrict__ Wm1, const float* __restrict__ bm1,
                      const float* __restrict__ Wm2, const float* __restrict__ bm2,
                      float* __restrict__ out)
{
    __shared__ float hs[32];
    __shared__ float red[128];
    int g = blockIdx.x;
    int t = threadIdx.x;
    if (t < 32) hs[t] = g_hn[g * 32 + t];
    __syncthreads();
    float a = bm1[t];
#pragma unroll
    for (int k = 0; k < 32; k++) a = fmaf(hs[k], Wm1[k * 128 + t], a);
    a = (a > 0.0f ? a : 0.0f) * Wm2[t];
    red[t] = a;
    __syncthreads();
    for (int s = 64; s > 0; s >>= 1) {
        if (t < s) red[t] += red[t + s];
        __syncthreads();
    }
    if (t == 0) out[g] = red[0] + bm2[0];
}

// ======================= launch =======================
static void* symp(const void* sym) {
    void* p = nullptr;
    cudaGetSymbolAddress(&p, sym);
    return p;
}

extern "C" void kernel_launch(void* const* d_in, const int* in_sizes, int n_in,
                              void* d_out, int out_size)
{
    const float* x   = (const float*)d_in[0];
    const int*   ei  = (const int*)d_in[1];
    const int*   src = ei;
    const int*   dst = ei + NE;
    const float* W1 = (const float*)d_in[3],  *b1 = (const float*)d_in[4];
    const float* W2 = (const float*)d_in[5],  *b2 = (const float*)d_in[6];
    const float* W3 = (const float*)d_in[7],  *b3 = (const float*)d_in[8];
    const float* W4 = (const float*)d_in[9],  *b4 = (const float*)d_in[10];
    const float* W5 = (const float*)d_in[11], *b5 = (const float*)d_in[12];
    const float* Wih_f = (const float*)d_in[13], *Whh_f = (const float*)d_in[14];
    const float* bih_f = (const float*)d_in[15], *bhh_f = (const float*)d_in[16];
    const float* Wih_b = (const float*)d_in[17], *Whh_b = (const float*)d_in[18];
    const float* bih_b = (const float*)d_in[19], *bhh_b = (const float*)d_in[20];
    const float* Wm1 = (const float*)d_in[21], *bm1 = (const float*)d_in[22];
    const float* Wm2 = (const float*)d_in[23], *bm2 = (const float*)d_in[24];
    float* out = (float*)d_out;

    float* bufA = (float*)symp(g_bufA);
    float* bufB = (float*)symp(g_bufB);
    const __nv_bfloat16* Wh = (const __nv_bfloat16*)symp(g_Wh);
    const __nv_bfloat16* Wl = (const __nv_bfloat16*)symp(g_Wl);

    cudaFuncSetAttribute(k_mma, cudaFuncAttributeMaxDynamicSharedMemorySize, SMEM_TOTAL);

    dim3 cw1(KP1 / 32, 8), cw2(256 / 32, 8), cwt(32, 8);

    // launches 0..3 — k_mma layer 1 lands on profiled slot (index 3)
    k_zero_deg<<<(NN + 255) / 256, 256>>>();                 // 0
    k_count<<<NE / 256, 256>>>(dst);                         // 1
    k_convW<<<cw1, cwt>>>(W1, 3000, KP1);                    // 2
    k_mma<<<NN / MT, 512, SMEM_TOTAL>>>(x, Wh, Wl, bufA, 3000, KP1);  // 3 <- profiled

    // graph prep (needed before first aggregation)
    k_nodeprep<<<(NN + 255) / 256, 256>>>();
    k_scan1<<<90, 256>>>();
    k_scan2<<<1, 128>>>();
    k_scan3<<<90, 256>>>();
    k_scatter<<<NE / 256, 256>>>(src, dst);

    k_agg256<<<NN / 4, 256>>>(bufA, b1, bufB);

    // layers 2-4 (K=256)
    const float* Ws[3] = {W2, W3, W4};
    const float* bs[3] = {b2, b3, b4};
    for (int l = 0; l < 3; l++) {
        k_convW<<<cw2, cwt>>>(Ws[l], 256, 256);
        k_mma<<<NN / MT, 512, SMEM_TOTAL>>>(bufB, Wh, Wl, bufA, 256, 256);
        k_agg256<<<NN / 4, 256>>>(bufA, bs[l], bufB);
    }
    // layer 5
    k_gemm16<<<NN / 16, 256>>>(bufB, W5);
    k_agg16<<<NN / 16, 256>>>((const float*)symp(g_g16), b5, (float*)symp(g_h5));

    // LSTM
    k_lstm_pre<<<NN / 128, 256>>>(Wih_f, bih_f, bhh_f, Wih_b, bih_b, bhh_b);
    k_lstm_rec<<<32, 128>>>(Whh_f, Whh_b);

    // MLP head
    k_mlp<<<NG, 128>>>(Wm1, bm1, Wm2, bm2, out);
}